// round 14
// baseline (speedup 1.0000x reference)
#include <cuda_runtime.h>
#include <math.h>

// ---------------------------------------------------------------------------
//  x:      (16, 3, 16, 128, 128)
//  h1:     (16, 4,  8,  64,  64)   conv k4 s2 p1 + relu
//  h2:     (16, 8,  4,  32,  32)   conv k4 s2 p1 + relu
//  z:      (16,16,  4,  32,  32)   conv k3 s1 p1 + clip[0,6]
//  d1:     (16, 8,  8,  64,  64)   deconv k4 s2 p1 + relu
//  d2:     (16, 4, 16, 128, 128)   deconv k4 s2 p1 + relu
//  out:    (16, 3, 16, 128, 128)   deconv k3 s1 p1
// ---------------------------------------------------------------------------

#define OUT_ELEMS (16*3*16*128*128)
#define NPOS      (16*4*32*32)
#define ZC        16
#define NCODE     32

typedef unsigned long long u64;

__device__ __forceinline__ u64 pack2(float lo, float hi) {
    u64 r; asm("mov.b64 %0, {%1,%2};" : "=l"(r) : "f"(lo), "f"(hi)); return r;
}
__device__ __forceinline__ void unpack2(u64 v, float& lo, float& hi) {
    asm("mov.b64 {%0,%1}, %2;" : "=f"(lo), "=f"(hi) : "l"(v));
}
__device__ __forceinline__ void fma2(u64& d, u64 a, u64 b) {
    asm("fma.rn.f32x2 %0, %1, %2, %0;" : "+l"(d) : "l"(a), "l"(b));
}

__device__ float g_h1[16*4*8*64*64];
__device__ float g_h2[16*8*4*32*32];
__device__ float g_z [16*16*4*32*32];
__device__ float g_q [16*16*4*32*32];
__device__ float g_d1[16*8*8*64*64];
__device__ float g_d2[16*4*16*128*128];
__device__ float g_sqsum;
__device__ int   g_hist[NCODE];

// ========================= conv1 (R14: co-split q, 2 co/thread) =============================
// x (16,3,16,128,128) -> h1 (16,4,8,64,64), k4 s2 p1, relu
// idx bits: wg(4) | b_lo(1) | q(1) | h(6) | d(3) | b_hi(3). 262144 thr, 2048x128
__global__ __launch_bounds__(128) void conv1_kernel(
    const float* __restrict__ x, const float* __restrict__ w,
    const float* __restrict__ bias, float* __restrict__ out)
{
    if (blockIdx.x == 0) {
        if (threadIdx.x == 0) g_sqsum = 0.f;
        if (threadIdx.x < NCODE) g_hist[threadIdx.x] = 0;
    }

    __shared__ __align__(16) float sw[768];   // [ci3][kd4][kh4][p2][kw4][lane2]
    __shared__ float sb[4];
    for (int i = threadIdx.x; i < 768; i += blockDim.x) {
        int lane = i & 1, kw = (i >> 1) & 3, p = (i >> 3) & 1,
            kh = (i >> 4) & 3, kd = (i >> 6) & 3, ci = i >> 8;
        int co = 2*p + lane;
        sw[i] = w[(((co*3+ci)*4+kd)*4+kh)*4+kw];
    }
    if (threadIdx.x < 4) sb[threadIdx.x] = bias[threadIdx.x];
    __syncthreads();
    const u64* sw8 = (const u64*)sw;

    int idx = blockIdx.x * blockDim.x + threadIdx.x;
    int wg = idx & 15;
    int bl = (idx >> 4) & 1;
    int q  = (idx >> 5) & 1;       // co pair (warp-uniform)
    int h  = (idx >> 6) & 63;
    int d  = (idx >> 12) & 7;
    int b  = ((idx >> 15) << 1) | bl;

    u64 acc[4];
    {
        u64 bv = pack2(sb[2*q], sb[2*q+1]);
        #pragma unroll
        for (int j = 0; j < 4; j++) acc[j] = bv;
    }

    for (int ci = 0; ci < 3; ci++) {
        const float* inc = x + (long long)(b*3+ci) * 16 * 16384;
        #pragma unroll
        for (int kd = 0; kd < 4; kd++) {
            int id = 2*d - 1 + kd;
            bool vd = (unsigned)id < 16u;
            const float* incd = inc + (vd ? id : 0) * 16384;
            #pragma unroll
            for (int kh = 0; kh < 4; kh++) {
                int ih = 2*h - 1 + kh;
                bool vh = (unsigned)ih < 128u;
                bool v = vd && vh;
                const float* row = incd + (vh ? ih : 0)*128 + 8*wg;
                float4 A = *(const float4*)row;
                float4 B = *(const float4*)(row + 4);
                if (!v) { A.x=0.f;A.y=0.f;A.z=0.f;A.w=0.f; B=A; }
                float lv = __shfl_up_sync(0xffffffffu, B.w, 1, 16);
                float rv = __shfl_down_sync(0xffffffffu, A.x, 1, 16);
                if (wg == 0)  lv = 0.f;
                if (wg == 15) rv = 0.f;
                u64 s[10];
                s[0]=pack2(lv,lv);  s[1]=pack2(A.x,A.x); s[2]=pack2(A.y,A.y);
                s[3]=pack2(A.z,A.z); s[4]=pack2(A.w,A.w); s[5]=pack2(B.x,B.x);
                s[6]=pack2(B.y,B.y); s[7]=pack2(B.z,B.z); s[8]=pack2(B.w,B.w);
                s[9]=pack2(rv,rv);
                int base = (((ci*4+kd)*4+kh)*2 + q)*4;
                const ulonglong2* wp = (const ulonglong2*)(sw8 + base);
                ulonglong2 WA = wp[0], WB = wp[1];
                u64 wk[4] = {WA.x, WA.y, WB.x, WB.y};
                #pragma unroll
                for (int kw = 0; kw < 4; kw++)
                    #pragma unroll
                    for (int j = 0; j < 4; j++)
                        fma2(acc[j], s[2*j+kw], wk[kw]);
            }
        }
    }
    float lo[4], hi[4];
    #pragma unroll
    for (int j = 0; j < 4; j++) unpack2(acc[j], lo[j], hi[j]);
    float4 r0, r1;
    r0.x = fmaxf(lo[0],0.f); r0.y = fmaxf(lo[1],0.f); r0.z = fmaxf(lo[2],0.f); r0.w = fmaxf(lo[3],0.f);
    r1.x = fmaxf(hi[0],0.f); r1.y = fmaxf(hi[1],0.f); r1.z = fmaxf(hi[2],0.f); r1.w = fmaxf(hi[3],0.f);
    int co = 2*q;
    *(float4*)&out[(long long)((b*4+co  )*8+d)*4096 + h*64 + 4*wg] = r0;
    *(float4*)&out[(long long)((b*4+co+1)*8+d)*4096 + h*64 + 4*wg] = r1;
}

// ========================= conv2 =============================
// h1 (16,4,8,64,64) -> h2 (16,8,4,32,32), k4 s2 p1, relu
// idx bits: wg(4) | q(2) | h(5) | d(2) | b(4). 131072 thr, 1024x128
__global__ __launch_bounds__(128) void conv2_kernel(
    const float* __restrict__ in, const float* __restrict__ w,
    const float* __restrict__ bias, float* __restrict__ out)
{
    __shared__ __align__(16) float sw[2048];   // [ci4][kd4][kh4][q4][kw4][lane2]
    __shared__ float sb[8];
    for (int i = threadIdx.x; i < 2048; i += blockDim.x) {
        int lane = i & 1, kw = (i >> 1) & 3, q = (i >> 3) & 3,
            kh = (i >> 5) & 3, kd = (i >> 7) & 3, ci = i >> 9;
        int co = 2*q + lane;
        sw[i] = w[(((co*4+ci)*4+kd)*4+kh)*4+kw];
    }
    if (threadIdx.x < 8) sb[threadIdx.x] = bias[threadIdx.x];
    __syncthreads();
    const u64* sw8 = (const u64*)sw;

    int idx = blockIdx.x * blockDim.x + threadIdx.x;
    int wg = idx & 15;           // wo0 = 2*wg
    int q  = (idx >> 4) & 3;     // co pair
    int h  = (idx >> 6) & 31;
    int d  = (idx >> 11) & 3;
    int b  = idx >> 13;

    u64 acc[2];
    {
        u64 bv = pack2(sb[2*q], sb[2*q+1]);
        acc[0] = bv; acc[1] = bv;
    }

    #pragma unroll
    for (int ci = 0; ci < 4; ci++) {
        const float* inc = in + (long long)((b*4+ci)*8) * 4096;
        #pragma unroll
        for (int kd = 0; kd < 4; kd++) {
            int id = 2*d - 1 + kd;
            bool vd = (unsigned)id < 8u;
            const float* incd = inc + (vd ? id : 0) * 4096;
            #pragma unroll
            for (int kh = 0; kh < 4; kh++) {
                int ih = 2*h - 1 + kh;
                bool vh = (unsigned)ih < 64u;
                bool v = vd && vh;
                const float* row = incd + (vh ? ih : 0)*64 + 4*wg;
                float4 A = *(const float4*)row;
                if (!v) { A.x=0.f;A.y=0.f;A.z=0.f;A.w=0.f; }
                float lv = __shfl_up_sync(0xffffffffu, A.w, 1, 16);
                float rv = __shfl_down_sync(0xffffffffu, A.x, 1, 16);
                if (wg == 0)  lv = 0.f;
                if (wg == 15) rv = 0.f;
                u64 s[6];
                s[0]=pack2(lv,lv); s[1]=pack2(A.x,A.x); s[2]=pack2(A.y,A.y);
                s[3]=pack2(A.z,A.z); s[4]=pack2(A.w,A.w); s[5]=pack2(rv,rv);
                int base = (((ci*4+kd)*4+kh)*4+q)*4;
                const ulonglong2* wp = (const ulonglong2*)(sw8 + base);
                ulonglong2 WA = wp[0], WB = wp[1];
                u64 wk[4] = {WA.x, WA.y, WB.x, WB.y};
                #pragma unroll
                for (int kw = 0; kw < 4; kw++) {
                    fma2(acc[0], s[kw],   wk[kw]);
                    fma2(acc[1], s[2+kw], wk[kw]);
                }
            }
        }
    }
    float a0,b0,a1,b1;
    unpack2(acc[0], a0, b0);
    unpack2(acc[1], a1, b1);
    int co = 2*q;
    float2 r0, r1;
    r0.x = fmaxf(a0,0.f); r0.y = fmaxf(a1,0.f);
    r1.x = fmaxf(b0,0.f); r1.y = fmaxf(b1,0.f);
    *(float2*)&out[(long long)((b*8+co  )*4+d)*1024 + h*32 + 2*wg] = r0;
    *(float2*)&out[(long long)((b*8+co+1)*4+d)*1024 + h*32 + 2*wg] = r1;
}

// ========================= conv3 =============================
// h2 (16,8,4,32,32) -> z (16,16,4,32,32), k3 s1 p1, clip[0,6]
// idx bits: wg(3) | q(3) | h(5) | d(2) | b(4). 131072 thr, 1024x128
__global__ __launch_bounds__(128) void conv3_kernel(
    const float* __restrict__ in, const float* __restrict__ w,
    const float* __restrict__ bias, float* __restrict__ out)
{
    __shared__ __align__(16) float sw[3456];   // [ci8][kd3][kh3][q8][kw3][lane2]
    __shared__ float sb[16];
    for (int i = threadIdx.x; i < 3456; i += blockDim.x) {
        int lane = i & 1;
        int r = i >> 1;
        int kw = r % 3; r /= 3;
        int q = r & 7; r >>= 3;
        int kh = r % 3; r /= 3;
        int kd = r % 3;
        int ci = r / 3;
        int co = 2*q + lane;
        sw[i] = w[(((co*8+ci)*3+kd)*3+kh)*3+kw];
    }
    if (threadIdx.x < 16) sb[threadIdx.x] = bias[threadIdx.x];
    __syncthreads();
    const u64* sw8 = (const u64*)sw;

    int idx = blockIdx.x * blockDim.x + threadIdx.x;
    int wg = idx & 7;            // wo0 = 4*wg
    int q  = (idx >> 3) & 7;     // co pair
    int h  = (idx >> 6) & 31;
    int d  = (idx >> 11) & 3;
    int b  = idx >> 13;

    u64 acc[4];
    {
        u64 bv = pack2(sb[2*q], sb[2*q+1]);
        #pragma unroll
        for (int j = 0; j < 4; j++) acc[j] = bv;
    }

    #pragma unroll
    for (int ci = 0; ci < 8; ci++) {
        const float* inc = in + (long long)((b*8+ci)*4) * 1024;
        #pragma unroll
        for (int kd = 0; kd < 3; kd++) {
            int id = d - 1 + kd;
            bool vd = (unsigned)id < 4u;
            const float* incd = inc + (vd ? id : 0) * 1024;
            #pragma unroll
            for (int kh = 0; kh < 3; kh++) {
                int ih = h - 1 + kh;
                bool vh = (unsigned)ih < 32u;
                bool v = vd && vh;
                const float* row = incd + (vh ? ih : 0)*32 + 4*wg;
                float4 A = *(const float4*)row;
                if (!v) { A.x=0.f;A.y=0.f;A.z=0.f;A.w=0.f; }
                float lv = __shfl_up_sync(0xffffffffu, A.w, 1, 8);
                float rv = __shfl_down_sync(0xffffffffu, A.x, 1, 8);
                if (wg == 0) lv = 0.f;
                if (wg == 7) rv = 0.f;
                u64 s[6];
                s[0]=pack2(lv,lv); s[1]=pack2(A.x,A.x); s[2]=pack2(A.y,A.y);
                s[3]=pack2(A.z,A.z); s[4]=pack2(A.w,A.w); s[5]=pack2(rv,rv);
                int base = ((((ci*3+kd)*3+kh)*8+q))*3;
                u64 wk0 = sw8[base], wk1 = sw8[base + 1], wk2 = sw8[base + 2];
                #pragma unroll
                for (int j = 0; j < 4; j++) {
                    fma2(acc[j], s[j],   wk0);
                    fma2(acc[j], s[j+1], wk1);
                    fma2(acc[j], s[j+2], wk2);
                }
            }
        }
    }
    float lo[4], hi[4];
    #pragma unroll
    for (int j = 0; j < 4; j++) unpack2(acc[j], lo[j], hi[j]);
    float4 r0, r1;
    r0.x = fminf(fmaxf(lo[0],0.f),6.f); r0.y = fminf(fmaxf(lo[1],0.f),6.f);
    r0.z = fminf(fmaxf(lo[2],0.f),6.f); r0.w = fminf(fmaxf(lo[3],0.f),6.f);
    r1.x = fminf(fmaxf(hi[0],0.f),6.f); r1.y = fminf(fmaxf(hi[1],0.f),6.f);
    r1.z = fminf(fmaxf(hi[2],0.f),6.f); r1.w = fminf(fmaxf(hi[3],0.f),6.f);
    int co = 2*q;
    *(float4*)&out[(long long)((b*16+co  )*4+d)*1024 + h*32 + 4*wg] = r0;
    *(float4*)&out[(long long)((b*16+co+1)*4+d)*1024 + h*32 + 4*wg] = r1;
}

// ========================= VQ (R14: 2 threads/position, code-split) =============================
// idx: bit0 = sub (codes 16*sub..16*sub+15), idx>>1 = position. 131072 thr, 1024x128
__global__ __launch_bounds__(128) void vq_kernel(
    const float* __restrict__ z, const float* __restrict__ emb_in,
    float* __restrict__ quant, float* __restrict__ codes_out)
{
    __shared__ float se[NCODE * ZC];
    __shared__ float sn[NCODE];
    __shared__ int   sh[NCODE];
    int tid = threadIdx.x;

    for (int i = tid; i < NCODE * ZC; i += blockDim.x) {
        int row = i / ZC;
        float v = __ldg(&emb_in[i]);
        if (row == 0) v = 0.f;
        if (row == 1) v = 6.f;
        se[i] = v;
    }
    if (tid < NCODE) sh[tid] = 0;
    __syncthreads();
    if (tid < NCODE) {
        float s = 0.f;
        for (int c = 0; c < ZC; c++) { float v = se[tid * ZC + c]; s += v * v; }
        sn[tid] = s;
    }
    __syncthreads();

    int idx = blockIdx.x * blockDim.x + tid;
    int sub = idx & 1;
    int p = idx >> 1;            // 0..65535
    int b = p >> 12;
    int s = p & 4095;
    const float* zb = z + (long long)(b * ZC) * 4096 + s;

    float f[ZC];
    float fn = 0.f;
    #pragma unroll
    for (int c = 0; c < ZC; c++) { f[c] = zb[(long long)c * 4096]; fn += f[c] * f[c]; }

    int e0 = sub * 16;
    int best = e0; float bestd = INFINITY;
    #pragma unroll
    for (int t = 0; t < 16; t++) {
        int e = e0 + t;
        float dot = 0.f;
        #pragma unroll
        for (int c = 0; c < ZC; c++) dot += f[c] * se[e * ZC + c];
        float dval = fn - 2.f * dot + sn[e];
        if (dval < bestd) { bestd = dval; best = e; }
    }
    // pair-reduce (partner lane = lane^1): pick min d, tie -> lower index
    float od = __shfl_xor_sync(0xffffffffu, bestd, 1);
    int   oe = __shfl_xor_sync(0xffffffffu, best, 1);
    if (od < bestd || (od == bestd && oe < best)) { bestd = od; best = oe; }

    // each sub handles half the channels for quant write + diff2
    float* qb = quant + (long long)(b * ZC) * 4096 + s;
    float diff2 = 0.f;
    int c0 = sub * 8;
    #pragma unroll
    for (int c = 0; c < 8; c++) {
        float e = se[best * ZC + c0 + c];
        qb[(long long)(c0 + c) * 4096] = e;
        float dvv = e - f[c0 + c];
        diff2 += dvv * dvv;
    }
    if (sub == 0) {
        codes_out[p] = (float)best;
        atomicAdd(&sh[best], 1);
    }
    #pragma unroll
    for (int o = 16; o > 0; o >>= 1) diff2 += __shfl_down_sync(0xffffffff, diff2, o);
    if ((tid & 31) == 0) atomicAdd(&g_sqsum, diff2);
    __syncthreads();
    if (tid < NCODE) atomicAdd(&g_hist[tid], sh[tid]);
}

// ========================= deconv1 (+ finalize fold) =============================
// q (16,16,4,32,32) -> d1 (16,8,8,64,64), k4 s2 p1, relu
// idx bits: wg(4) | b_lo(1) | ho(6) | dd(3) | b_hi(3). 131072 thr, 1024x128
__global__ __launch_bounds__(128) void deconv1_kernel(
    const float* __restrict__ in, const float* __restrict__ w,
    const float* __restrict__ bias, float* __restrict__ out,
    const float* __restrict__ cluster_size, float* __restrict__ final_out)
{
    if (blockIdx.x == 0 && threadIdx.x == 0) {
        float invN = 1.f / (float)NPOS;
        float ent = 0.f;
        int used = 0;
        for (int i = 0; i < NCODE; i++) {
            float p = (float)g_hist[i] * invN;
            ent += p * logf(p + 1e-10f);
            if (__ldg(&cluster_size[i]) > 1e-5f) used++;
        }
        final_out[OUT_ELEMS] = 0.25f * g_sqsum / (float)(NPOS * ZC);
        final_out[OUT_ELEMS + 1 + NPOS] = expf(-ent);
        final_out[OUT_ELEMS + 2 + NPOS] = (float)used / (float)NCODE;
    }

    __shared__ __align__(16) float sw[8192];   // [ci16][kd4][kh4][p4][kw4][lane2]
    __shared__ float sb[8];
    for (int i = threadIdx.x; i < 8192; i += blockDim.x) {
        int lane = i & 1, kw = (i >> 1) & 3, p = (i >> 3) & 3,
            kh = (i >> 5) & 3, kd = (i >> 7) & 3, ci = i >> 9;
        int co = 2*p + lane;
        sw[i] = w[(((ci*8+co)*4+kd)*4+kh)*4+kw];
    }
    if (threadIdx.x < 8) sb[threadIdx.x] = bias[threadIdx.x];
    __syncthreads();
    const u64* sw8 = (const u64*)sw;

    int idx = blockIdx.x * blockDim.x + threadIdx.x;
    int wg = idx & 15;           // w0 = 4*wg
    int bl = (idx >> 4) & 1;
    int ho = (idx >> 5) & 63;
    int dd = (idx >> 11) & 7;
    int b  = ((idx >> 14) << 1) | bl;

    int ida = (dd + 1) >> 1, kda = (dd + 1) & 1;
    int iha = (ho + 1) >> 1, kha = (ho + 1) & 1;

    u64 acc[4][4];
    #pragma unroll
    for (int p = 0; p < 4; p++) {
        u64 bv = pack2(sb[2*p], sb[2*p+1]);
        #pragma unroll
        for (int j = 0; j < 4; j++) acc[p][j] = bv;
    }

    #pragma unroll
    for (int dt = 0; dt < 2; dt++) {
        int id = ida - dt, kd = kda + 2*dt;
        bool vd = (unsigned)id < 4u;
        int idc = vd ? id : 0;
        #pragma unroll
        for (int ht = 0; ht < 2; ht++) {
            int ih = iha - ht, kh = kha + 2*ht;
            bool vh = (unsigned)ih < 32u;
            bool v = vd && vh;
            int ihc = vh ? ih : 0;
            #pragma unroll
            for (int ci = 0; ci < 16; ci++) {
                const float* row = in + (long long)((b*16+ci)*4+idc)*1024 + ihc*32 + 2*wg;
                float2 V = *(const float2*)row;
                if (!v) { V.x = 0.f; V.y = 0.f; }
                float lv = __shfl_up_sync(0xffffffffu, V.y, 1, 16);
                float rv = __shfl_down_sync(0xffffffffu, V.x, 1, 16);
                if (wg == 0)  lv = 0.f;
                if (wg == 15) rv = 0.f;
                u64 s[4];
                s[0]=pack2(lv,lv); s[1]=pack2(V.x,V.x); s[2]=pack2(V.y,V.y); s[3]=pack2(rv,rv);
                int base = (((ci*4+kd)*4+kh)*4)*4;
                #pragma unroll
                for (int p = 0; p < 4; p++) {
                    const ulonglong2* wp = (const ulonglong2*)(sw8 + base + p*4);
                    ulonglong2 A = wp[0], B = wp[1];
                    u64 wk0 = A.x, wk1 = A.y, wk2 = B.x, wk3 = B.y;
                    fma2(acc[p][0], s[1], wk1); fma2(acc[p][0], s[0], wk3);
                    fma2(acc[p][1], s[2], wk0); fma2(acc[p][1], s[1], wk2);
                    fma2(acc[p][2], s[2], wk1); fma2(acc[p][2], s[1], wk3);
                    fma2(acc[p][3], s[3], wk0); fma2(acc[p][3], s[2], wk2);
                }
            }
        }
    }
    #pragma unroll
    for (int p = 0; p < 4; p++) {
        float lo[4], hi[4];
        #pragma unroll
        for (int j = 0; j < 4; j++) unpack2(acc[p][j], lo[j], hi[j]);
        float4 r0, r1;
        r0.x = fmaxf(lo[0],0.f); r0.y = fmaxf(lo[1],0.f); r0.z = fmaxf(lo[2],0.f); r0.w = fmaxf(lo[3],0.f);
        r1.x = fmaxf(hi[0],0.f); r1.y = fmaxf(hi[1],0.f); r1.z = fmaxf(hi[2],0.f); r1.w = fmaxf(hi[3],0.f);
        *(float4*)&out[(long long)((b*8+2*p  )*8+dd)*4096 + ho*64 + 4*wg] = r0;
        *(float4*)&out[(long long)((b*8+2*p+1)*8+dd)*4096 + ho*64 + 4*wg] = r1;
    }
}

// ========================= deconv3 =============================
// d1 (16,8,8,64,64) -> d2 (16,4,16,128,128), k4 s2 p1, relu
// idx bits: wg(5) | ho(7) | dd(4) | b(4). 1048576 thr, 4096x256
__global__ __launch_bounds__(256) void deconv3_kernel(
    const float* __restrict__ in, const float* __restrict__ w,
    const float* __restrict__ bias, float* __restrict__ out)
{
    __shared__ __align__(16) float sw[2048];   // [ci8][kd4][kh4][p2][kw4][lane2]
    __shared__ float sb[4];
    for (int i = threadIdx.x; i < 2048; i += blockDim.x) {
        int lane = i & 1, kw = (i >> 1) & 3, p = (i >> 3) & 1,
            kh = (i >> 4) & 3, kd = (i >> 6) & 3, ci = i >> 8;
        int co = 2*p + lane;
        sw[i] = w[(((ci*4+co)*4+kd)*4+kh)*4+kw];
    }
    if (threadIdx.x < 4) sb[threadIdx.x] = bias[threadIdx.x];
    __syncthreads();
    const u64* sw8 = (const u64*)sw;

    int idx = blockIdx.x * blockDim.x + threadIdx.x;
    int wg = idx & 31;            // w0 = 4*wg, lane == wg
    int ho = (idx >> 5) & 127;
    int dd = (idx >> 12) & 15;
    int b  = idx >> 16;

    int ida = (dd + 1) >> 1, kda = (dd + 1) & 1;
    int iha = (ho + 1) >> 1, kha = (ho + 1) & 1;

    u64 acc[2][4];
    #pragma unroll
    for (int p = 0; p < 2; p++) {
        u64 bv = pack2(sb[2*p], sb[2*p+1]);
        #pragma unroll
        for (int j = 0; j < 4; j++) acc[p][j] = bv;
    }

    #pragma unroll
    for (int dt = 0; dt < 2; dt++) {
        int id = ida - dt, kd = kda + 2*dt;
        bool vd = (unsigned)id < 8u;
        int idc = vd ? id : 0;
        #pragma unroll
        for (int ht = 0; ht < 2; ht++) {
            int ih = iha - ht, kh = kha + 2*ht;
            bool vh = (unsigned)ih < 64u;
            bool v = vd && vh;
            int ihc = vh ? ih : 0;
            #pragma unroll
            for (int ci = 0; ci < 8; ci++) {
                const float* row = in + (long long)((b*8+ci)*8+idc)*4096 + ihc*64 + 2*wg;
                float2 V = *(const float2*)row;
                if (!v) { V.x = 0.f; V.y = 0.f; }
                float lv = __shfl_up_sync(0xffffffffu, V.y, 1);
                float rv = __shfl_down_sync(0xffffffffu, V.x, 1);
                if (wg == 0)  lv = 0.f;
                if (wg == 31) rv = 0.f;
                u64 s[4];
                s[0]=pack2(lv,lv); s[1]=pack2(V.x,V.x); s[2]=pack2(V.y,V.y); s[3]=pack2(rv,rv);
                int base = (((ci*4+kd)*4+kh)*2)*4;
                #pragma unroll
                for (int p = 0; p < 2; p++) {
                    const ulonglong2* wp = (const ulonglong2*)(sw8 + base + p*4);
                    ulonglong2 A = wp[0], B = wp[1];
                    u64 wk0 = A.x, wk1 = A.y, wk2 = B.x, wk3 = B.y;
                    fma2(acc[p][0], s[1], wk1); fma2(acc[p][0], s[0], wk3);
                    fma2(acc[p][1], s[2], wk0); fma2(acc[p][1], s[1], wk2);
                    fma2(acc[p][2], s[2], wk1); fma2(acc[p][2], s[1], wk3);
                    fma2(acc[p][3], s[3], wk0); fma2(acc[p][3], s[2], wk2);
                }
            }
        }
    }
    #pragma unroll
    for (int p = 0; p < 2; p++) {
        float lo[4], hi[4];
        #pragma unroll
        for (int j = 0; j < 4; j++) unpack2(acc[p][j], lo[j], hi[j]);
        float4 r0, r1;
        r0.x = fmaxf(lo[0],0.f); r0.y = fmaxf(lo[1],0.f); r0.z = fmaxf(lo[2],0.f); r0.w = fmaxf(lo[3],0.f);
        r1.x = fmaxf(hi[0],0.f); r1.y = fmaxf(hi[1],0.f); r1.z = fmaxf(hi[2],0.f); r1.w = fmaxf(hi[3],0.f);
        *(float4*)&out[(long long)((b*4+2*p  )*16+dd)*16384 + ho*128 + 4*wg] = r0;
        *(float4*)&out[(long long)((b*4+2*p+1)*16+dd)*16384 + ho*128 + 4*wg] = r1;
    }
}

// ========================= deconv4 =============================
// d2 (16,4,16,128,128) -> out (16,3,16,128,128), k3 s1 p1, linear
// idx bits: wg(5) | ho(7) | dd(4) | b(4). 1048576 thr, 4096x256
__global__ __launch_bounds__(256) void deconv4_kernel(
    const float* __restrict__ in, const float* __restrict__ w,
    const float* __restrict__ bias, float* __restrict__ out)
{
    __shared__ __align__(16) float sw[576];   // [ci4][kd3][kh3][p2][kw4pad][lane2]
    __shared__ float sb[4];
    for (int i = threadIdx.x; i < 576; i += blockDim.x) {
        int lane = i & 1, kw = (i >> 1) & 3, p = (i >> 3) & 1;
        int r = i >> 4;
        int kh = r % 3; r /= 3;
        int kd = r % 3;
        int ci = r / 3;
        int co = 2*p + lane;
        sw[i] = (kw < 3 && co < 3) ? w[(((ci*3+co)*3+kd)*3+kh)*3+kw] : 0.f;
    }
    if (threadIdx.x < 4) sb[threadIdx.x] = (threadIdx.x < 3) ? bias[threadIdx.x] : 0.f;
    __syncthreads();
    const u64* sw8 = (const u64*)sw;

    int idx = blockIdx.x * blockDim.x + threadIdx.x;
    int wg = idx & 31;           // w0 = 4*wg, lane == wg
    int ho = (idx >> 5) & 127;
    int dd = (idx >> 12) & 15;
    int b  = idx >> 16;

    u64 acc[2][4];
    #pragma unroll
    for (int p = 0; p < 2; p++) {
        u64 bv = pack2(sb[2*p], sb[2*p+1]);
        #pragma unroll
        for (int j = 0; j < 4; j++) acc[p][j] = bv;
    }

    #pragma unroll
    for (int ci = 0; ci < 4; ci++) {
        const float* inc = in + (long long)((b*4+ci)*16) * 16384;
        #pragma unroll
        for (int kd = 0; kd < 3; kd++) {
            int id = dd + 1 - kd;
            bool vd = (unsigned)id < 16u;
            const float* incd = inc + (vd ? id : 0) * 16384;
            #pragma unroll
            for (int kh = 0; kh < 3; kh++) {
                int ih = ho + 1 - kh;
                bool vh = (unsigned)ih < 128u;
                bool v = vd && vh;
                const float* row = incd + (vh ? ih : 0)*128 + 4*wg;
                float4 A = *(const float4*)row;
                if (!v) { A.x=0.f;A.y=0.f;A.z=0.f;A.w=0.f; }
                float lv = __shfl_up_sync(0xffffffffu, A.w, 1);
                float rv = __shfl_down_sync(0xffffffffu, A.x, 1);
                if (wg == 0)  lv = 0.f;
                if (wg == 31) rv = 0.f;
                u64 s[6];
                s[0]=pack2(lv,lv); s[1]=pack2(A.x,A.x); s[2]=pack2(A.y,A.y);
                s[3]=pack2(A.z,A.z); s[4]=pack2(A.w,A.w); s[5]=pack2(rv,rv);
                int base = (((ci*3+kd)*3+kh)*2)*4;
                #pragma unroll
                for (int p = 0; p < 2; p++) {
                    const ulonglong2* wp = (const ulonglong2*)(sw8 + base + p*4);
                    ulonglong2 WA = wp[0];
                    u64 wk0 = WA.x, wk1 = WA.y, wk2 = sw8[base + p*4 + 2];
                    #pragma unroll
                    for (int j = 0; j < 4; j++) {
                        fma2(acc[p][j], s[j+2], wk0);
                        fma2(acc[p][j], s[j+1], wk1);
                        fma2(acc[p][j], s[j],   wk2);
                    }
                }
            }
        }
    }
    float lo0[4], hi0[4], lo1[4], hi1[4];
    #pragma unroll
    for (int j = 0; j < 4; j++) { unpack2(acc[0][j], lo0[j], hi0[j]); unpack2(acc[1][j], lo1[j], hi1[j]); }
    *(float4*)&out[(long long)((b*3+0)*16+dd)*16384 + ho*128 + 4*wg] = make_float4(lo0[0],lo0[1],lo0[2],lo0[3]);
    *(float4*)&out[(long long)((b*3+1)*16+dd)*16384 + ho*128 + 4*wg] = make_float4(hi0[0],hi0[1],hi0[2],hi0[3]);
    *(float4*)&out[(long long)((b*3+2)*16+dd)*16384 + ho*128 + 4*wg] = make_float4(lo1[0],lo1[1],lo1[2],lo1[3]);
}

// ---------------------------------------------------------------------------
extern "C" void kernel_launch(void* const* d_in, const int* in_sizes, int n_in,
                              void* d_out, int out_size)
{
    const float* x       = (const float*)d_in[0];
    const float* enc_w1  = (const float*)d_in[2];
    const float* enc_b1  = (const float*)d_in[3];
    const float* enc_w2  = (const float*)d_in[4];
    const float* enc_b2  = (const float*)d_in[5];
    const float* enc_w4  = (const float*)d_in[6];
    const float* enc_b4  = (const float*)d_in[7];
    const float* dec_w1  = (const float*)d_in[8];
    const float* dec_b1  = (const float*)d_in[9];
    const float* dec_w3  = (const float*)d_in[10];
    const float* dec_b3  = (const float*)d_in[11];
    const float* dec_w4  = (const float*)d_in[12];
    const float* dec_b4  = (const float*)d_in[13];
    const float* emb     = (const float*)d_in[14];
    const float* clsz    = (const float*)d_in[15];
    float* out = (float*)d_out;

    float *h1, *h2, *z, *q, *d1, *d2;
    cudaGetSymbolAddress((void**)&h1, g_h1);
    cudaGetSymbolAddress((void**)&h2, g_h2);
    cudaGetSymbolAddress((void**)&z,  g_z);
    cudaGetSymbolAddress((void**)&q,  g_q);
    cudaGetSymbolAddress((void**)&d1, g_d1);
    cudaGetSymbolAddress((void**)&d2, g_d2);

    conv1_kernel<<<2048, 128>>>(x, enc_w1, enc_b1, h1);
    conv2_kernel<<<1024, 128>>>(h1, enc_w2, enc_b2, h2);
    conv3_kernel<<<1024, 128>>>(h2, enc_w4, enc_b4, z);

    vq_kernel<<<1024, 128>>>(z, emb, q, out + OUT_ELEMS + 1);

    deconv1_kernel<<<1024, 128>>>(q, dec_w1, dec_b1, d1, clsz, out);
    deconv3_kernel<<<4096, 256>>>(d1, dec_w3, dec_b3, d2);
    deconv4_kernel<<<4096, 256>>>(d2, dec_w4, dec_b4, out);
}

// round 15
// speedup vs baseline: 1.0194x; 1.0194x over previous
#include <cuda_runtime.h>
#include <math.h>

// ---------------------------------------------------------------------------
//  x:      (16, 3, 16, 128, 128)
//  h1:     (16, 4,  8,  64,  64)   conv k4 s2 p1 + relu
//  h2:     (16, 8,  4,  32,  32)   conv k4 s2 p1 + relu
//  z:      (16,16,  4,  32,  32)   conv k3 s1 p1 + clip[0,6]
//  d1:     (16, 8,  8,  64,  64)   deconv k4 s2 p1 + relu
//  d2:     (16, 4, 16, 128, 128)   deconv k4 s2 p1 + relu
//  out:    (16, 3, 16, 128, 128)   deconv k3 s1 p1
// ---------------------------------------------------------------------------

#define OUT_ELEMS (16*3*16*128*128)
#define NPOS      (16*4*32*32)
#define ZC        16
#define NCODE     32

typedef unsigned long long u64;

__device__ __forceinline__ u64 pack2(float lo, float hi) {
    u64 r; asm("mov.b64 %0, {%1,%2};" : "=l"(r) : "f"(lo), "f"(hi)); return r;
}
__device__ __forceinline__ void unpack2(u64 v, float& lo, float& hi) {
    asm("mov.b64 {%0,%1}, %2;" : "=f"(lo), "=f"(hi) : "l"(v));
}
__device__ __forceinline__ void fma2(u64& d, u64 a, u64 b) {
    asm("fma.rn.f32x2 %0, %1, %2, %0;" : "+l"(d) : "l"(a), "l"(b));
}

__device__ float g_h1[16*4*8*64*64];
__device__ float g_h2[16*8*4*32*32];
__device__ float g_z [16*16*4*32*32];
__device__ float g_q [16*16*4*32*32];
__device__ float g_d1[16*8*8*64*64];
__device__ float g_d2[16*4*16*128*128];
__device__ float g_sqsum;
__device__ int   g_hist[NCODE];

// ========================= conv1 (R13) =============================
// x (16,3,16,128,128) -> h1 (16,4,8,64,64), k4 s2 p1, relu
// idx bits: wg(4) | b_lo(1) | h(6) | d(3) | b_hi(3). 131072 thr, 1024x128
__global__ __launch_bounds__(128) void conv1_kernel(
    const float* __restrict__ x, const float* __restrict__ w,
    const float* __restrict__ bias, float* __restrict__ out)
{
    if (blockIdx.x == 0) {
        if (threadIdx.x == 0) g_sqsum = 0.f;
        if (threadIdx.x < NCODE) g_hist[threadIdx.x] = 0;
    }

    __shared__ __align__(16) float sw[768];   // [ci3][kd4][kh4][p2][kw4][lane2]
    __shared__ float sb[4];
    for (int i = threadIdx.x; i < 768; i += blockDim.x) {
        int lane = i & 1, kw = (i >> 1) & 3, p = (i >> 3) & 1,
            kh = (i >> 4) & 3, kd = (i >> 6) & 3, ci = i >> 8;
        int co = 2*p + lane;
        sw[i] = w[(((co*3+ci)*4+kd)*4+kh)*4+kw];
    }
    if (threadIdx.x < 4) sb[threadIdx.x] = bias[threadIdx.x];
    __syncthreads();
    const u64* sw8 = (const u64*)sw;

    int idx = blockIdx.x * blockDim.x + threadIdx.x;
    int wg = idx & 15;
    int bl = (idx >> 4) & 1;
    int h  = (idx >> 5) & 63;
    int d  = (idx >> 11) & 7;
    int b  = ((idx >> 14) << 1) | bl;

    u64 acc[2][4];
    #pragma unroll
    for (int p = 0; p < 2; p++) {
        u64 bv = pack2(sb[2*p], sb[2*p+1]);
        #pragma unroll
        for (int j = 0; j < 4; j++) acc[p][j] = bv;
    }

    for (int ci = 0; ci < 3; ci++) {
        const float* inc = x + (long long)(b*3+ci) * 16 * 16384;
        #pragma unroll
        for (int kd = 0; kd < 4; kd++) {
            int id = 2*d - 1 + kd;
            bool vd = (unsigned)id < 16u;
            const float* incd = inc + (vd ? id : 0) * 16384;
            #pragma unroll
            for (int kh = 0; kh < 4; kh++) {
                int ih = 2*h - 1 + kh;
                bool vh = (unsigned)ih < 128u;
                bool v = vd && vh;
                const float* row = incd + (vh ? ih : 0)*128 + 8*wg;
                float4 A = *(const float4*)row;
                float4 B = *(const float4*)(row + 4);
                if (!v) { A.x=0.f;A.y=0.f;A.z=0.f;A.w=0.f; B=A; }
                float lv = __shfl_up_sync(0xffffffffu, B.w, 1, 16);
                float rv = __shfl_down_sync(0xffffffffu, A.x, 1, 16);
                if (wg == 0)  lv = 0.f;
                if (wg == 15) rv = 0.f;
                u64 s[10];
                s[0]=pack2(lv,lv);  s[1]=pack2(A.x,A.x); s[2]=pack2(A.y,A.y);
                s[3]=pack2(A.z,A.z); s[4]=pack2(A.w,A.w); s[5]=pack2(B.x,B.x);
                s[6]=pack2(B.y,B.y); s[7]=pack2(B.z,B.z); s[8]=pack2(B.w,B.w);
                s[9]=pack2(rv,rv);
                int base = (((ci*4+kd)*4+kh)*2)*4;
                #pragma unroll
                for (int p = 0; p < 2; p++) {
                    const ulonglong2* wp = (const ulonglong2*)(sw8 + base + p*4);
                    ulonglong2 WA = wp[0], WB = wp[1];
                    u64 wk[4] = {WA.x, WA.y, WB.x, WB.y};
                    #pragma unroll
                    for (int kw = 0; kw < 4; kw++)
                        #pragma unroll
                        for (int j = 0; j < 4; j++)
                            fma2(acc[p][j], s[2*j+kw], wk[kw]);
                }
            }
        }
    }
    #pragma unroll
    for (int p = 0; p < 2; p++) {
        float lo[4], hi[4];
        #pragma unroll
        for (int j = 0; j < 4; j++) unpack2(acc[p][j], lo[j], hi[j]);
        float4 r0, r1;
        r0.x = fmaxf(lo[0],0.f); r0.y = fmaxf(lo[1],0.f); r0.z = fmaxf(lo[2],0.f); r0.w = fmaxf(lo[3],0.f);
        r1.x = fmaxf(hi[0],0.f); r1.y = fmaxf(hi[1],0.f); r1.z = fmaxf(hi[2],0.f); r1.w = fmaxf(hi[3],0.f);
        *(float4*)&out[(long long)((b*4+2*p  )*8+d)*4096 + h*64 + 4*wg] = r0;
        *(float4*)&out[(long long)((b*4+2*p+1)*8+d)*4096 + h*64 + 4*wg] = r1;
    }
}

// ========================= conv2 (R13) =============================
// h1 (16,4,8,64,64) -> h2 (16,8,4,32,32), k4 s2 p1, relu
// idx bits: wg(4) | q(2) | h(5) | d(2) | b(4). 131072 thr, 1024x128
__global__ __launch_bounds__(128) void conv2_kernel(
    const float* __restrict__ in, const float* __restrict__ w,
    const float* __restrict__ bias, float* __restrict__ out)
{
    __shared__ __align__(16) float sw[2048];   // [ci4][kd4][kh4][q4][kw4][lane2]
    __shared__ float sb[8];
    for (int i = threadIdx.x; i < 2048; i += blockDim.x) {
        int lane = i & 1, kw = (i >> 1) & 3, q = (i >> 3) & 3,
            kh = (i >> 5) & 3, kd = (i >> 7) & 3, ci = i >> 9;
        int co = 2*q + lane;
        sw[i] = w[(((co*4+ci)*4+kd)*4+kh)*4+kw];
    }
    if (threadIdx.x < 8) sb[threadIdx.x] = bias[threadIdx.x];
    __syncthreads();
    const u64* sw8 = (const u64*)sw;

    int idx = blockIdx.x * blockDim.x + threadIdx.x;
    int wg = idx & 15;           // wo0 = 2*wg
    int q  = (idx >> 4) & 3;     // co pair
    int h  = (idx >> 6) & 31;
    int d  = (idx >> 11) & 3;
    int b  = idx >> 13;

    u64 acc[2];
    {
        u64 bv = pack2(sb[2*q], sb[2*q+1]);
        acc[0] = bv; acc[1] = bv;
    }

    #pragma unroll
    for (int ci = 0; ci < 4; ci++) {
        const float* inc = in + (long long)((b*4+ci)*8) * 4096;
        #pragma unroll
        for (int kd = 0; kd < 4; kd++) {
            int id = 2*d - 1 + kd;
            bool vd = (unsigned)id < 8u;
            const float* incd = inc + (vd ? id : 0) * 4096;
            #pragma unroll
            for (int kh = 0; kh < 4; kh++) {
                int ih = 2*h - 1 + kh;
                bool vh = (unsigned)ih < 64u;
                bool v = vd && vh;
                const float* row = incd + (vh ? ih : 0)*64 + 4*wg;
                float4 A = *(const float4*)row;
                if (!v) { A.x=0.f;A.y=0.f;A.z=0.f;A.w=0.f; }
                float lv = __shfl_up_sync(0xffffffffu, A.w, 1, 16);
                float rv = __shfl_down_sync(0xffffffffu, A.x, 1, 16);
                if (wg == 0)  lv = 0.f;
                if (wg == 15) rv = 0.f;
                u64 s[6];
                s[0]=pack2(lv,lv); s[1]=pack2(A.x,A.x); s[2]=pack2(A.y,A.y);
                s[3]=pack2(A.z,A.z); s[4]=pack2(A.w,A.w); s[5]=pack2(rv,rv);
                int base = (((ci*4+kd)*4+kh)*4+q)*4;
                const ulonglong2* wp = (const ulonglong2*)(sw8 + base);
                ulonglong2 WA = wp[0], WB = wp[1];
                u64 wk[4] = {WA.x, WA.y, WB.x, WB.y};
                #pragma unroll
                for (int kw = 0; kw < 4; kw++) {
                    fma2(acc[0], s[kw],   wk[kw]);
                    fma2(acc[1], s[2+kw], wk[kw]);
                }
            }
        }
    }
    float a0,b0,a1,b1;
    unpack2(acc[0], a0, b0);
    unpack2(acc[1], a1, b1);
    int co = 2*q;
    float2 r0, r1;
    r0.x = fmaxf(a0,0.f); r0.y = fmaxf(a1,0.f);
    r1.x = fmaxf(b0,0.f); r1.y = fmaxf(b1,0.f);
    *(float2*)&out[(long long)((b*8+co  )*4+d)*1024 + h*32 + 2*wg] = r0;
    *(float2*)&out[(long long)((b*8+co+1)*4+d)*1024 + h*32 + 2*wg] = r1;
}

// ========================= conv3 (R13) =============================
// h2 (16,8,4,32,32) -> z (16,16,4,32,32), k3 s1 p1, clip[0,6]
// idx bits: wg(3) | q(3) | h(5) | d(2) | b(4). 131072 thr, 1024x128
__global__ __launch_bounds__(128) void conv3_kernel(
    const float* __restrict__ in, const float* __restrict__ w,
    const float* __restrict__ bias, float* __restrict__ out)
{
    __shared__ __align__(16) float sw[3456];   // [ci8][kd3][kh3][q8][kw3][lane2]
    __shared__ float sb[16];
    for (int i = threadIdx.x; i < 3456; i += blockDim.x) {
        int lane = i & 1;
        int r = i >> 1;
        int kw = r % 3; r /= 3;
        int q = r & 7; r >>= 3;
        int kh = r % 3; r /= 3;
        int kd = r % 3;
        int ci = r / 3;
        int co = 2*q + lane;
        sw[i] = w[(((co*8+ci)*3+kd)*3+kh)*3+kw];
    }
    if (threadIdx.x < 16) sb[threadIdx.x] = bias[threadIdx.x];
    __syncthreads();
    const u64* sw8 = (const u64*)sw;

    int idx = blockIdx.x * blockDim.x + threadIdx.x;
    int wg = idx & 7;            // wo0 = 4*wg
    int q  = (idx >> 3) & 7;     // co pair
    int h  = (idx >> 6) & 31;
    int d  = (idx >> 11) & 3;
    int b  = idx >> 13;

    u64 acc[4];
    {
        u64 bv = pack2(sb[2*q], sb[2*q+1]);
        #pragma unroll
        for (int j = 0; j < 4; j++) acc[j] = bv;
    }

    #pragma unroll
    for (int ci = 0; ci < 8; ci++) {
        const float* inc = in + (long long)((b*8+ci)*4) * 1024;
        #pragma unroll
        for (int kd = 0; kd < 3; kd++) {
            int id = d - 1 + kd;
            bool vd = (unsigned)id < 4u;
            const float* incd = inc + (vd ? id : 0) * 1024;
            #pragma unroll
            for (int kh = 0; kh < 3; kh++) {
                int ih = h - 1 + kh;
                bool vh = (unsigned)ih < 32u;
                bool v = vd && vh;
                const float* row = incd + (vh ? ih : 0)*32 + 4*wg;
                float4 A = *(const float4*)row;
                if (!v) { A.x=0.f;A.y=0.f;A.z=0.f;A.w=0.f; }
                float lv = __shfl_up_sync(0xffffffffu, A.w, 1, 8);
                float rv = __shfl_down_sync(0xffffffffu, A.x, 1, 8);
                if (wg == 0) lv = 0.f;
                if (wg == 7) rv = 0.f;
                u64 s[6];
                s[0]=pack2(lv,lv); s[1]=pack2(A.x,A.x); s[2]=pack2(A.y,A.y);
                s[3]=pack2(A.z,A.z); s[4]=pack2(A.w,A.w); s[5]=pack2(rv,rv);
                int base = ((((ci*3+kd)*3+kh)*8+q))*3;
                u64 wk0 = sw8[base], wk1 = sw8[base + 1], wk2 = sw8[base + 2];
                #pragma unroll
                for (int j = 0; j < 4; j++) {
                    fma2(acc[j], s[j],   wk0);
                    fma2(acc[j], s[j+1], wk1);
                    fma2(acc[j], s[j+2], wk2);
                }
            }
        }
    }
    float lo[4], hi[4];
    #pragma unroll
    for (int j = 0; j < 4; j++) unpack2(acc[j], lo[j], hi[j]);
    float4 r0, r1;
    r0.x = fminf(fmaxf(lo[0],0.f),6.f); r0.y = fminf(fmaxf(lo[1],0.f),6.f);
    r0.z = fminf(fmaxf(lo[2],0.f),6.f); r0.w = fminf(fmaxf(lo[3],0.f),6.f);
    r1.x = fminf(fmaxf(hi[0],0.f),6.f); r1.y = fminf(fmaxf(hi[1],0.f),6.f);
    r1.z = fminf(fmaxf(hi[2],0.f),6.f); r1.w = fminf(fmaxf(hi[3],0.f),6.f);
    int co = 2*q;
    *(float4*)&out[(long long)((b*16+co  )*4+d)*1024 + h*32 + 4*wg] = r0;
    *(float4*)&out[(long long)((b*16+co+1)*4+d)*1024 + h*32 + 4*wg] = r1;
}

// ========================= VQ (R15: channel-split, 2 thr/pos) =============================
// idx: bit0 = sub (channels 8*sub..8*sub+7), idx>>1 = position. 131072 thr, 1024x128
// Total z traffic unchanged vs 1-thr/pos (each thread loads only its 8 channels);
// per-code partial dots combined with shfl_xor(1); both lanes see identical
// full distances -> identical argmin.
__global__ __launch_bounds__(128) void vq_kernel(
    const float* __restrict__ z, const float* __restrict__ emb_in,
    float* __restrict__ quant, float* __restrict__ codes_out)
{
    __shared__ float se[NCODE * ZC];
    __shared__ float sn[NCODE];
    __shared__ int   sh[NCODE];
    int tid = threadIdx.x;

    for (int i = tid; i < NCODE * ZC; i += blockDim.x) {
        int row = i / ZC;
        float v = __ldg(&emb_in[i]);
        if (row == 0) v = 0.f;
        if (row == 1) v = 6.f;
        se[i] = v;
    }
    if (tid < NCODE) sh[tid] = 0;
    __syncthreads();
    if (tid < NCODE) {
        float s = 0.f;
        for (int c = 0; c < ZC; c++) { float v = se[tid * ZC + c]; s += v * v; }
        sn[tid] = s;
    }
    __syncthreads();

    int idx = blockIdx.x * blockDim.x + tid;
    int sub = idx & 1;
    int p = idx >> 1;            // 0..65535
    int b = p >> 12;
    int s = p & 4095;
    int c0 = sub * 8;
    const float* zb = z + (long long)(b * ZC + c0) * 4096 + s;

    float f[8];
    float fnp = 0.f;
    #pragma unroll
    for (int c = 0; c < 8; c++) { f[c] = zb[(long long)c * 4096]; fnp += f[c] * f[c]; }
    float fn = fnp + __shfl_xor_sync(0xffffffffu, fnp, 1);

    int best = 0; float bestd = INFINITY;
    for (int e = 0; e < NCODE; e++) {
        float dp = 0.f;
        #pragma unroll
        for (int c = 0; c < 8; c++) dp += f[c] * se[e * ZC + c0 + c];
        float dot = dp + __shfl_xor_sync(0xffffffffu, dp, 1);
        float dval = fn - 2.f * dot + sn[e];
        if (dval < bestd) { bestd = dval; best = e; }   // identical on both lanes
    }

    // each sub writes its 8 channels of quant + partial diff2
    float* qb = quant + (long long)(b * ZC + c0) * 4096 + s;
    float diff2 = 0.f;
    #pragma unroll
    for (int c = 0; c < 8; c++) {
        float e = se[best * ZC + c0 + c];
        qb[(long long)c * 4096] = e;
        float dvv = e - f[c];
        diff2 += dvv * dvv;
    }
    if (sub == 0) {
        codes_out[p] = (float)best;
        atomicAdd(&sh[best], 1);
    }
    #pragma unroll
    for (int o = 16; o > 0; o >>= 1) diff2 += __shfl_down_sync(0xffffffff, diff2, o);
    if ((tid & 31) == 0) atomicAdd(&g_sqsum, diff2);
    __syncthreads();
    if (tid < NCODE) atomicAdd(&g_hist[tid], sh[tid]);
}

// ========================= deconv1 (R13, + finalize fold) =============================
// q (16,16,4,32,32) -> d1 (16,8,8,64,64), k4 s2 p1, relu
// idx bits: wg(4) | b_lo(1) | ho(6) | dd(3) | b_hi(3). 131072 thr, 1024x128
__global__ __launch_bounds__(128) void deconv1_kernel(
    const float* __restrict__ in, const float* __restrict__ w,
    const float* __restrict__ bias, float* __restrict__ out,
    const float* __restrict__ cluster_size, float* __restrict__ final_out)
{
    if (blockIdx.x == 0 && threadIdx.x == 0) {
        float invN = 1.f / (float)NPOS;
        float ent = 0.f;
        int used = 0;
        for (int i = 0; i < NCODE; i++) {
            float p = (float)g_hist[i] * invN;
            ent += p * logf(p + 1e-10f);
            if (__ldg(&cluster_size[i]) > 1e-5f) used++;
        }
        final_out[OUT_ELEMS] = 0.25f * g_sqsum / (float)(NPOS * ZC);
        final_out[OUT_ELEMS + 1 + NPOS] = expf(-ent);
        final_out[OUT_ELEMS + 2 + NPOS] = (float)used / (float)NCODE;
    }

    __shared__ __align__(16) float sw[8192];   // [ci16][kd4][kh4][p4][kw4][lane2]
    __shared__ float sb[8];
    for (int i = threadIdx.x; i < 8192; i += blockDim.x) {
        int lane = i & 1, kw = (i >> 1) & 3, p = (i >> 3) & 3,
            kh = (i >> 5) & 3, kd = (i >> 7) & 3, ci = i >> 9;
        int co = 2*p + lane;
        sw[i] = w[(((ci*8+co)*4+kd)*4+kh)*4+kw];
    }
    if (threadIdx.x < 8) sb[threadIdx.x] = bias[threadIdx.x];
    __syncthreads();
    const u64* sw8 = (const u64*)sw;

    int idx = blockIdx.x * blockDim.x + threadIdx.x;
    int wg = idx & 15;           // w0 = 4*wg
    int bl = (idx >> 4) & 1;
    int ho = (idx >> 5) & 63;
    int dd = (idx >> 11) & 7;
    int b  = ((idx >> 14) << 1) | bl;

    int ida = (dd + 1) >> 1, kda = (dd + 1) & 1;
    int iha = (ho + 1) >> 1, kha = (ho + 1) & 1;

    u64 acc[4][4];
    #pragma unroll
    for (int p = 0; p < 4; p++) {
        u64 bv = pack2(sb[2*p], sb[2*p+1]);
        #pragma unroll
        for (int j = 0; j < 4; j++) acc[p][j] = bv;
    }

    #pragma unroll
    for (int dt = 0; dt < 2; dt++) {
        int id = ida - dt, kd = kda + 2*dt;
        bool vd = (unsigned)id < 4u;
        int idc = vd ? id : 0;
        #pragma unroll
        for (int ht = 0; ht < 2; ht++) {
            int ih = iha - ht, kh = kha + 2*ht;
            bool vh = (unsigned)ih < 32u;
            bool v = vd && vh;
            int ihc = vh ? ih : 0;
            #pragma unroll
            for (int ci = 0; ci < 16; ci++) {
                const float* row = in + (long long)((b*16+ci)*4+idc)*1024 + ihc*32 + 2*wg;
                float2 V = *(const float2*)row;
                if (!v) { V.x = 0.f; V.y = 0.f; }
                float lv = __shfl_up_sync(0xffffffffu, V.y, 1, 16);
                float rv = __shfl_down_sync(0xffffffffu, V.x, 1, 16);
                if (wg == 0)  lv = 0.f;
                if (wg == 15) rv = 0.f;
                u64 s[4];
                s[0]=pack2(lv,lv); s[1]=pack2(V.x,V.x); s[2]=pack2(V.y,V.y); s[3]=pack2(rv,rv);
                int base = (((ci*4+kd)*4+kh)*4)*4;
                #pragma unroll
                for (int p = 0; p < 4; p++) {
                    const ulonglong2* wp = (const ulonglong2*)(sw8 + base + p*4);
                    ulonglong2 A = wp[0], B = wp[1];
                    u64 wk0 = A.x, wk1 = A.y, wk2 = B.x, wk3 = B.y;
                    fma2(acc[p][0], s[1], wk1); fma2(acc[p][0], s[0], wk3);
                    fma2(acc[p][1], s[2], wk0); fma2(acc[p][1], s[1], wk2);
                    fma2(acc[p][2], s[2], wk1); fma2(acc[p][2], s[1], wk3);
                    fma2(acc[p][3], s[3], wk0); fma2(acc[p][3], s[2], wk2);
                }
            }
        }
    }
    #pragma unroll
    for (int p = 0; p < 4; p++) {
        float lo[4], hi[4];
        #pragma unroll
        for (int j = 0; j < 4; j++) unpack2(acc[p][j], lo[j], hi[j]);
        float4 r0, r1;
        r0.x = fmaxf(lo[0],0.f); r0.y = fmaxf(lo[1],0.f); r0.z = fmaxf(lo[2],0.f); r0.w = fmaxf(lo[3],0.f);
        r1.x = fmaxf(hi[0],0.f); r1.y = fmaxf(hi[1],0.f); r1.z = fmaxf(hi[2],0.f); r1.w = fmaxf(hi[3],0.f);
        *(float4*)&out[(long long)((b*8+2*p  )*8+dd)*4096 + ho*64 + 4*wg] = r0;
        *(float4*)&out[(long long)((b*8+2*p+1)*8+dd)*4096 + ho*64 + 4*wg] = r1;
    }
}

// ========================= deconv3 (R13) =============================
// d1 (16,8,8,64,64) -> d2 (16,4,16,128,128), k4 s2 p1, relu
// idx bits: wg(5) | ho(7) | dd(4) | b(4). 1048576 thr, 4096x256
__global__ __launch_bounds__(256) void deconv3_kernel(
    const float* __restrict__ in, const float* __restrict__ w,
    const float* __restrict__ bias, float* __restrict__ out)
{
    __shared__ __align__(16) float sw[2048];   // [ci8][kd4][kh4][p2][kw4][lane2]
    __shared__ float sb[4];
    for (int i = threadIdx.x; i < 2048; i += blockDim.x) {
        int lane = i & 1, kw = (i >> 1) & 3, p = (i >> 3) & 1,
            kh = (i >> 4) & 3, kd = (i >> 6) & 3, ci = i >> 8;
        int co = 2*p + lane;
        sw[i] = w[(((ci*4+co)*4+kd)*4+kh)*4+kw];
    }
    if (threadIdx.x < 4) sb[threadIdx.x] = bias[threadIdx.x];
    __syncthreads();
    const u64* sw8 = (const u64*)sw;

    int idx = blockIdx.x * blockDim.x + threadIdx.x;
    int wg = idx & 31;            // w0 = 4*wg, lane == wg
    int ho = (idx >> 5) & 127;
    int dd = (idx >> 12) & 15;
    int b  = idx >> 16;

    int ida = (dd + 1) >> 1, kda = (dd + 1) & 1;
    int iha = (ho + 1) >> 1, kha = (ho + 1) & 1;

    u64 acc[2][4];
    #pragma unroll
    for (int p = 0; p < 2; p++) {
        u64 bv = pack2(sb[2*p], sb[2*p+1]);
        #pragma unroll
        for (int j = 0; j < 4; j++) acc[p][j] = bv;
    }

    #pragma unroll
    for (int dt = 0; dt < 2; dt++) {
        int id = ida - dt, kd = kda + 2*dt;
        bool vd = (unsigned)id < 8u;
        int idc = vd ? id : 0;
        #pragma unroll
        for (int ht = 0; ht < 2; ht++) {
            int ih = iha - ht, kh = kha + 2*ht;
            bool vh = (unsigned)ih < 64u;
            bool v = vd && vh;
            int ihc = vh ? ih : 0;
            #pragma unroll
            for (int ci = 0; ci < 8; ci++) {
                const float* row = in + (long long)((b*8+ci)*8+idc)*4096 + ihc*64 + 2*wg;
                float2 V = *(const float2*)row;
                if (!v) { V.x = 0.f; V.y = 0.f; }
                float lv = __shfl_up_sync(0xffffffffu, V.y, 1);
                float rv = __shfl_down_sync(0xffffffffu, V.x, 1);
                if (wg == 0)  lv = 0.f;
                if (wg == 31) rv = 0.f;
                u64 s[4];
                s[0]=pack2(lv,lv); s[1]=pack2(V.x,V.x); s[2]=pack2(V.y,V.y); s[3]=pack2(rv,rv);
                int base = (((ci*4+kd)*4+kh)*2)*4;
                #pragma unroll
                for (int p = 0; p < 2; p++) {
                    const ulonglong2* wp = (const ulonglong2*)(sw8 + base + p*4);
                    ulonglong2 A = wp[0], B = wp[1];
                    u64 wk0 = A.x, wk1 = A.y, wk2 = B.x, wk3 = B.y;
                    fma2(acc[p][0], s[1], wk1); fma2(acc[p][0], s[0], wk3);
                    fma2(acc[p][1], s[2], wk0); fma2(acc[p][1], s[1], wk2);
                    fma2(acc[p][2], s[2], wk1); fma2(acc[p][2], s[1], wk3);
                    fma2(acc[p][3], s[3], wk0); fma2(acc[p][3], s[2], wk2);
                }
            }
        }
    }
    #pragma unroll
    for (int p = 0; p < 2; p++) {
        float lo[4], hi[4];
        #pragma unroll
        for (int j = 0; j < 4; j++) unpack2(acc[p][j], lo[j], hi[j]);
        float4 r0, r1;
        r0.x = fmaxf(lo[0],0.f); r0.y = fmaxf(lo[1],0.f); r0.z = fmaxf(lo[2],0.f); r0.w = fmaxf(lo[3],0.f);
        r1.x = fmaxf(hi[0],0.f); r1.y = fmaxf(hi[1],0.f); r1.z = fmaxf(hi[2],0.f); r1.w = fmaxf(hi[3],0.f);
        *(float4*)&out[(long long)((b*4+2*p  )*16+dd)*16384 + ho*128 + 4*wg] = r0;
        *(float4*)&out[(long long)((b*4+2*p+1)*16+dd)*16384 + ho*128 + 4*wg] = r1;
    }
}

// ========================= deconv4 (R13) =============================
// d2 (16,4,16,128,128) -> out (16,3,16,128,128), k3 s1 p1, linear
// idx bits: wg(5) | ho(7) | dd(4) | b(4). 1048576 thr, 4096x256
__global__ __launch_bounds__(256) void deconv4_kernel(
    const float* __restrict__ in, const float* __restrict__ w,
    const float* __restrict__ bias, float* __restrict__ out)
{
    __shared__ __align__(16) float sw[576];   // [ci4][kd3][kh3][p2][kw4pad][lane2]
    __shared__ float sb[4];
    for (int i = threadIdx.x; i < 576; i += blockDim.x) {
        int lane = i & 1, kw = (i >> 1) & 3, p = (i >> 3) & 1;
        int r = i >> 4;
        int kh = r % 3; r /= 3;
        int kd = r % 3;
        int ci = r / 3;
        int co = 2*p + lane;
        sw[i] = (kw < 3 && co < 3) ? w[(((ci*3+co)*3+kd)*3+kh)*3+kw] : 0.f;
    }
    if (threadIdx.x < 4) sb[threadIdx.x] = (threadIdx.x < 3) ? bias[threadIdx.x] : 0.f;
    __syncthreads();
    const u64* sw8 = (const u64*)sw;

    int idx = blockIdx.x * blockDim.x + threadIdx.x;
    int wg = idx & 31;           // w0 = 4*wg, lane == wg
    int ho = (idx >> 5) & 127;
    int dd = (idx >> 12) & 15;
    int b  = idx >> 16;

    u64 acc[2][4];
    #pragma unroll
    for (int p = 0; p < 2; p++) {
        u64 bv = pack2(sb[2*p], sb[2*p+1]);
        #pragma unroll
        for (int j = 0; j < 4; j++) acc[p][j] = bv;
    }

    #pragma unroll
    for (int ci = 0; ci < 4; ci++) {
        const float* inc = in + (long long)((b*4+ci)*16) * 16384;
        #pragma unroll
        for (int kd = 0; kd < 3; kd++) {
            int id = dd + 1 - kd;
            bool vd = (unsigned)id < 16u;
            const float* incd = inc + (vd ? id : 0) * 16384;
            #pragma unroll
            for (int kh = 0; kh < 3; kh++) {
                int ih = ho + 1 - kh;
                bool vh = (unsigned)ih < 128u;
                bool v = vd && vh;
                const float* row = incd + (vh ? ih : 0)*128 + 4*wg;
                float4 A = *(const float4*)row;
                if (!v) { A.x=0.f;A.y=0.f;A.z=0.f;A.w=0.f; }
                float lv = __shfl_up_sync(0xffffffffu, A.w, 1);
                float rv = __shfl_down_sync(0xffffffffu, A.x, 1);
                if (wg == 0)  lv = 0.f;
                if (wg == 31) rv = 0.f;
                u64 s[6];
                s[0]=pack2(lv,lv); s[1]=pack2(A.x,A.x); s[2]=pack2(A.y,A.y);
                s[3]=pack2(A.z,A.z); s[4]=pack2(A.w,A.w); s[5]=pack2(rv,rv);
                int base = (((ci*3+kd)*3+kh)*2)*4;
                #pragma unroll
                for (int p = 0; p < 2; p++) {
                    const ulonglong2* wp = (const ulonglong2*)(sw8 + base + p*4);
                    ulonglong2 WA = wp[0];
                    u64 wk0 = WA.x, wk1 = WA.y, wk2 = sw8[base + p*4 + 2];
                    #pragma unroll
                    for (int j = 0; j < 4; j++) {
                        fma2(acc[p][j], s[j+2], wk0);
                        fma2(acc[p][j], s[j+1], wk1);
                        fma2(acc[p][j], s[j],   wk2);
                    }
                }
            }
        }
    }
    float lo0[4], hi0[4], lo1[4], hi1[4];
    #pragma unroll
    for (int j = 0; j < 4; j++) { unpack2(acc[0][j], lo0[j], hi0[j]); unpack2(acc[1][j], lo1[j], hi1[j]); }
    *(float4*)&out[(long long)((b*3+0)*16+dd)*16384 + ho*128 + 4*wg] = make_float4(lo0[0],lo0[1],lo0[2],lo0[3]);
    *(float4*)&out[(long long)((b*3+1)*16+dd)*16384 + ho*128 + 4*wg] = make_float4(hi0[0],hi0[1],hi0[2],hi0[3]);
    *(float4*)&out[(long long)((b*3+2)*16+dd)*16384 + ho*128 + 4*wg] = make_float4(lo1[0],lo1[1],lo1[2],lo1[3]);
}

// ---------------------------------------------------------------------------
extern "C" void kernel_launch(void* const* d_in, const int* in_sizes, int n_in,
                              void* d_out, int out_size)
{
    const float* x       = (const float*)d_in[0];
    const float* enc_w1  = (const float*)d_in[2];
    const float* enc_b1  = (const float*)d_in[3];
    const float* enc_w2  = (const float*)d_in[4];
    const float* enc_b2  = (const float*)d_in[5];
    const float* enc_w4  = (const float*)d_in[6];
    const float* enc_b4  = (const float*)d_in[7];
    const float* dec_w1  = (const float*)d_in[8];
    const float* dec_b1  = (const float*)d_in[9];
    const float* dec_w3  = (const float*)d_in[10];
    const float* dec_b3  = (const float*)d_in[11];
    const float* dec_w4  = (const float*)d_in[12];
    const float* dec_b4  = (const float*)d_in[13];
    const float* emb     = (const float*)d_in[14];
    const float* clsz    = (const float*)d_in[15];
    float* out = (float*)d_out;

    float *h1, *h2, *z, *q, *d1, *d2;
    cudaGetSymbolAddress((void**)&h1, g_h1);
    cudaGetSymbolAddress((void**)&h2, g_h2);
    cudaGetSymbolAddress((void**)&z,  g_z);
    cudaGetSymbolAddress((void**)&q,  g_q);
    cudaGetSymbolAddress((void**)&d1, g_d1);
    cudaGetSymbolAddress((void**)&d2, g_d2);

    conv1_kernel<<<1024, 128>>>(x, enc_w1, enc_b1, h1);
    conv2_kernel<<<1024, 128>>>(h1, enc_w2, enc_b2, h2);
    conv3_kernel<<<1024, 128>>>(h2, enc_w4, enc_b4, z);

    vq_kernel<<<1024, 128>>>(z, emb, q, out + OUT_ELEMS + 1);

    deconv1_kernel<<<1024, 128>>>(q, dec_w1, dec_b1, d1, clsz, out);
    deconv3_kernel<<<4096, 256>>>(d1, dec_w3, dec_b3, d2);
    deconv4_kernel<<<4096, 256>>>(d2, dec_w4, dec_b4, out);
}

// round 16
// speedup vs baseline: 1.0330x; 1.0134x over previous
#include <cuda_runtime.h>
#include <math.h>

// ---------------------------------------------------------------------------
//  x:      (16, 3, 16, 128, 128)
//  h1:     (16, 4,  8,  64,  64)   conv k4 s2 p1 + relu
//  h2:     (16, 8,  4,  32,  32)   conv k4 s2 p1 + relu
//  z:      (16,16,  4,  32,  32)   conv k3 s1 p1 + clip[0,6]
//  d1:     (16, 8,  8,  64,  64)   deconv k4 s2 p1 + relu
//  d2:     (16, 4, 16, 128, 128)   deconv k4 s2 p1 + relu
//  out:    (16, 3, 16, 128, 128)   deconv k3 s1 p1
// ---------------------------------------------------------------------------

#define OUT_ELEMS (16*3*16*128*128)
#define NPOS      (16*4*32*32)
#define ZC        16
#define NCODE     32

typedef unsigned long long u64;

__device__ __forceinline__ u64 pack2(float lo, float hi) {
    u64 r; asm("mov.b64 %0, {%1,%2};" : "=l"(r) : "f"(lo), "f"(hi)); return r;
}
__device__ __forceinline__ void unpack2(u64 v, float& lo, float& hi) {
    asm("mov.b64 {%0,%1}, %2;" : "=f"(lo), "=f"(hi) : "l"(v));
}
__device__ __forceinline__ void fma2(u64& d, u64 a, u64 b) {
    asm("fma.rn.f32x2 %0, %1, %2, %0;" : "+l"(d) : "l"(a), "l"(b));
}

__device__ float g_h1[16*4*8*64*64];
__device__ float g_h2[16*8*4*32*32];
__device__ float g_z [16*16*4*32*32];
__device__ float g_q [16*16*4*32*32];
__device__ float g_d1[16*8*8*64*64];
__device__ float g_d2[16*4*16*128*128];
__device__ float g_sqsum;
__device__ int   g_hist[NCODE];

// ========================= conv1 (R13) =============================
// x (16,3,16,128,128) -> h1 (16,4,8,64,64), k4 s2 p1, relu
// idx bits: wg(4) | b_lo(1) | h(6) | d(3) | b_hi(3). 131072 thr, 1024x128
__global__ __launch_bounds__(128) void conv1_kernel(
    const float* __restrict__ x, const float* __restrict__ w,
    const float* __restrict__ bias, float* __restrict__ out)
{
    if (blockIdx.x == 0) {
        if (threadIdx.x == 0) g_sqsum = 0.f;
        if (threadIdx.x < NCODE) g_hist[threadIdx.x] = 0;
    }

    __shared__ __align__(16) float sw[768];   // [ci3][kd4][kh4][p2][kw4][lane2]
    __shared__ float sb[4];
    for (int i = threadIdx.x; i < 768; i += blockDim.x) {
        int lane = i & 1, kw = (i >> 1) & 3, p = (i >> 3) & 1,
            kh = (i >> 4) & 3, kd = (i >> 6) & 3, ci = i >> 8;
        int co = 2*p + lane;
        sw[i] = w[(((co*3+ci)*4+kd)*4+kh)*4+kw];
    }
    if (threadIdx.x < 4) sb[threadIdx.x] = bias[threadIdx.x];
    __syncthreads();
    const u64* sw8 = (const u64*)sw;

    int idx = blockIdx.x * blockDim.x + threadIdx.x;
    int wg = idx & 15;
    int bl = (idx >> 4) & 1;
    int h  = (idx >> 5) & 63;
    int d  = (idx >> 11) & 7;
    int b  = ((idx >> 14) << 1) | bl;

    u64 acc[2][4];
    #pragma unroll
    for (int p = 0; p < 2; p++) {
        u64 bv = pack2(sb[2*p], sb[2*p+1]);
        #pragma unroll
        for (int j = 0; j < 4; j++) acc[p][j] = bv;
    }

    for (int ci = 0; ci < 3; ci++) {
        const float* inc = x + (long long)(b*3+ci) * 16 * 16384;
        #pragma unroll
        for (int kd = 0; kd < 4; kd++) {
            int id = 2*d - 1 + kd;
            bool vd = (unsigned)id < 16u;
            const float* incd = inc + (vd ? id : 0) * 16384;
            #pragma unroll
            for (int kh = 0; kh < 4; kh++) {
                int ih = 2*h - 1 + kh;
                bool vh = (unsigned)ih < 128u;
                bool v = vd && vh;
                const float* row = incd + (vh ? ih : 0)*128 + 8*wg;
                float4 A = *(const float4*)row;
                float4 B = *(const float4*)(row + 4);
                if (!v) { A.x=0.f;A.y=0.f;A.z=0.f;A.w=0.f; B=A; }
                float lv = __shfl_up_sync(0xffffffffu, B.w, 1, 16);
                float rv = __shfl_down_sync(0xffffffffu, A.x, 1, 16);
                if (wg == 0)  lv = 0.f;
                if (wg == 15) rv = 0.f;
                u64 s[10];
                s[0]=pack2(lv,lv);  s[1]=pack2(A.x,A.x); s[2]=pack2(A.y,A.y);
                s[3]=pack2(A.z,A.z); s[4]=pack2(A.w,A.w); s[5]=pack2(B.x,B.x);
                s[6]=pack2(B.y,B.y); s[7]=pack2(B.z,B.z); s[8]=pack2(B.w,B.w);
                s[9]=pack2(rv,rv);
                int base = (((ci*4+kd)*4+kh)*2)*4;
                #pragma unroll
                for (int p = 0; p < 2; p++) {
                    const ulonglong2* wp = (const ulonglong2*)(sw8 + base + p*4);
                    ulonglong2 WA = wp[0], WB = wp[1];
                    u64 wk[4] = {WA.x, WA.y, WB.x, WB.y};
                    #pragma unroll
                    for (int kw = 0; kw < 4; kw++)
                        #pragma unroll
                        for (int j = 0; j < 4; j++)
                            fma2(acc[p][j], s[2*j+kw], wk[kw]);
                }
            }
        }
    }
    #pragma unroll
    for (int p = 0; p < 2; p++) {
        float lo[4], hi[4];
        #pragma unroll
        for (int j = 0; j < 4; j++) unpack2(acc[p][j], lo[j], hi[j]);
        float4 r0, r1;
        r0.x = fmaxf(lo[0],0.f); r0.y = fmaxf(lo[1],0.f); r0.z = fmaxf(lo[2],0.f); r0.w = fmaxf(lo[3],0.f);
        r1.x = fmaxf(hi[0],0.f); r1.y = fmaxf(hi[1],0.f); r1.z = fmaxf(hi[2],0.f); r1.w = fmaxf(hi[3],0.f);
        *(float4*)&out[(long long)((b*4+2*p  )*8+d)*4096 + h*64 + 4*wg] = r0;
        *(float4*)&out[(long long)((b*4+2*p+1)*8+d)*4096 + h*64 + 4*wg] = r1;
    }
}

// ========================= conv2 (R13) =============================
// h1 (16,4,8,64,64) -> h2 (16,8,4,32,32), k4 s2 p1, relu
// idx bits: wg(4) | q(2) | h(5) | d(2) | b(4). 131072 thr, 1024x128
__global__ __launch_bounds__(128) void conv2_kernel(
    const float* __restrict__ in, const float* __restrict__ w,
    const float* __restrict__ bias, float* __restrict__ out)
{
    __shared__ __align__(16) float sw[2048];   // [ci4][kd4][kh4][q4][kw4][lane2]
    __shared__ float sb[8];
    for (int i = threadIdx.x; i < 2048; i += blockDim.x) {
        int lane = i & 1, kw = (i >> 1) & 3, q = (i >> 3) & 3,
            kh = (i >> 5) & 3, kd = (i >> 7) & 3, ci = i >> 9;
        int co = 2*q + lane;
        sw[i] = w[(((co*4+ci)*4+kd)*4+kh)*4+kw];
    }
    if (threadIdx.x < 8) sb[threadIdx.x] = bias[threadIdx.x];
    __syncthreads();
    const u64* sw8 = (const u64*)sw;

    int idx = blockIdx.x * blockDim.x + threadIdx.x;
    int wg = idx & 15;           // wo0 = 2*wg
    int q  = (idx >> 4) & 3;     // co pair
    int h  = (idx >> 6) & 31;
    int d  = (idx >> 11) & 3;
    int b  = idx >> 13;

    u64 acc[2];
    {
        u64 bv = pack2(sb[2*q], sb[2*q+1]);
        acc[0] = bv; acc[1] = bv;
    }

    #pragma unroll
    for (int ci = 0; ci < 4; ci++) {
        const float* inc = in + (long long)((b*4+ci)*8) * 4096;
        #pragma unroll
        for (int kd = 0; kd < 4; kd++) {
            int id = 2*d - 1 + kd;
            bool vd = (unsigned)id < 8u;
            const float* incd = inc + (vd ? id : 0) * 4096;
            #pragma unroll
            for (int kh = 0; kh < 4; kh++) {
                int ih = 2*h - 1 + kh;
                bool vh = (unsigned)ih < 64u;
                bool v = vd && vh;
                const float* row = incd + (vh ? ih : 0)*64 + 4*wg;
                float4 A = *(const float4*)row;
                if (!v) { A.x=0.f;A.y=0.f;A.z=0.f;A.w=0.f; }
                float lv = __shfl_up_sync(0xffffffffu, A.w, 1, 16);
                float rv = __shfl_down_sync(0xffffffffu, A.x, 1, 16);
                if (wg == 0)  lv = 0.f;
                if (wg == 15) rv = 0.f;
                u64 s[6];
                s[0]=pack2(lv,lv); s[1]=pack2(A.x,A.x); s[2]=pack2(A.y,A.y);
                s[3]=pack2(A.z,A.z); s[4]=pack2(A.w,A.w); s[5]=pack2(rv,rv);
                int base = (((ci*4+kd)*4+kh)*4+q)*4;
                const ulonglong2* wp = (const ulonglong2*)(sw8 + base);
                ulonglong2 WA = wp[0], WB = wp[1];
                u64 wk[4] = {WA.x, WA.y, WB.x, WB.y};
                #pragma unroll
                for (int kw = 0; kw < 4; kw++) {
                    fma2(acc[0], s[kw],   wk[kw]);
                    fma2(acc[1], s[2+kw], wk[kw]);
                }
            }
        }
    }
    float a0,b0,a1,b1;
    unpack2(acc[0], a0, b0);
    unpack2(acc[1], a1, b1);
    int co = 2*q;
    float2 r0, r1;
    r0.x = fmaxf(a0,0.f); r0.y = fmaxf(a1,0.f);
    r1.x = fmaxf(b0,0.f); r1.y = fmaxf(b1,0.f);
    *(float2*)&out[(long long)((b*8+co  )*4+d)*1024 + h*32 + 2*wg] = r0;
    *(float2*)&out[(long long)((b*8+co+1)*4+d)*1024 + h*32 + 2*wg] = r1;
}

// ========================= conv3 (R13) =============================
// h2 (16,8,4,32,32) -> z (16,16,4,32,32), k3 s1 p1, clip[0,6]
// idx bits: wg(3) | q(3) | h(5) | d(2) | b(4). 131072 thr, 1024x128
__global__ __launch_bounds__(128) void conv3_kernel(
    const float* __restrict__ in, const float* __restrict__ w,
    const float* __restrict__ bias, float* __restrict__ out)
{
    __shared__ __align__(16) float sw[3456];   // [ci8][kd3][kh3][q8][kw3][lane2]
    __shared__ float sb[16];
    for (int i = threadIdx.x; i < 3456; i += blockDim.x) {
        int lane = i & 1;
        int r = i >> 1;
        int kw = r % 3; r /= 3;
        int q = r & 7; r >>= 3;
        int kh = r % 3; r /= 3;
        int kd = r % 3;
        int ci = r / 3;
        int co = 2*q + lane;
        sw[i] = w[(((co*8+ci)*3+kd)*3+kh)*3+kw];
    }
    if (threadIdx.x < 16) sb[threadIdx.x] = bias[threadIdx.x];
    __syncthreads();
    const u64* sw8 = (const u64*)sw;

    int idx = blockIdx.x * blockDim.x + threadIdx.x;
    int wg = idx & 7;            // wo0 = 4*wg
    int q  = (idx >> 3) & 7;     // co pair
    int h  = (idx >> 6) & 31;
    int d  = (idx >> 11) & 3;
    int b  = idx >> 13;

    u64 acc[4];
    {
        u64 bv = pack2(sb[2*q], sb[2*q+1]);
        #pragma unroll
        for (int j = 0; j < 4; j++) acc[j] = bv;
    }

    #pragma unroll
    for (int ci = 0; ci < 8; ci++) {
        const float* inc = in + (long long)((b*8+ci)*4) * 1024;
        #pragma unroll
        for (int kd = 0; kd < 3; kd++) {
            int id = d - 1 + kd;
            bool vd = (unsigned)id < 4u;
            const float* incd = inc + (vd ? id : 0) * 1024;
            #pragma unroll
            for (int kh = 0; kh < 3; kh++) {
                int ih = h - 1 + kh;
                bool vh = (unsigned)ih < 32u;
                bool v = vd && vh;
                const float* row = incd + (vh ? ih : 0)*32 + 4*wg;
                float4 A = *(const float4*)row;
                if (!v) { A.x=0.f;A.y=0.f;A.z=0.f;A.w=0.f; }
                float lv = __shfl_up_sync(0xffffffffu, A.w, 1, 8);
                float rv = __shfl_down_sync(0xffffffffu, A.x, 1, 8);
                if (wg == 0) lv = 0.f;
                if (wg == 7) rv = 0.f;
                u64 s[6];
                s[0]=pack2(lv,lv); s[1]=pack2(A.x,A.x); s[2]=pack2(A.y,A.y);
                s[3]=pack2(A.z,A.z); s[4]=pack2(A.w,A.w); s[5]=pack2(rv,rv);
                int base = ((((ci*3+kd)*3+kh)*8+q))*3;
                u64 wk0 = sw8[base], wk1 = sw8[base + 1], wk2 = sw8[base + 2];
                #pragma unroll
                for (int j = 0; j < 4; j++) {
                    fma2(acc[j], s[j],   wk0);
                    fma2(acc[j], s[j+1], wk1);
                    fma2(acc[j], s[j+2], wk2);
                }
            }
        }
    }
    float lo[4], hi[4];
    #pragma unroll
    for (int j = 0; j < 4; j++) unpack2(acc[j], lo[j], hi[j]);
    float4 r0, r1;
    r0.x = fminf(fmaxf(lo[0],0.f),6.f); r0.y = fminf(fmaxf(lo[1],0.f),6.f);
    r0.z = fminf(fmaxf(lo[2],0.f),6.f); r0.w = fminf(fmaxf(lo[3],0.f),6.f);
    r1.x = fminf(fmaxf(hi[0],0.f),6.f); r1.y = fminf(fmaxf(hi[1],0.f),6.f);
    r1.z = fminf(fmaxf(hi[2],0.f),6.f); r1.w = fminf(fmaxf(hi[3],0.f),6.f);
    int co = 2*q;
    *(float4*)&out[(long long)((b*16+co  )*4+d)*1024 + h*32 + 4*wg] = r0;
    *(float4*)&out[(long long)((b*16+co+1)*4+d)*1024 + h*32 + 4*wg] = r1;
}

// ========================= VQ (R16: f32x2 code pairs) =============================
// 1 thread/position (as R13), 512 blocks x 128 thr. Distance dots for code pair
// (2e, 2e+1) accumulated with fma2; per-code accumulation order identical to R13.
__global__ __launch_bounds__(128) void vq_kernel(
    const float* __restrict__ z, const float* __restrict__ emb_in,
    float* __restrict__ quant, float* __restrict__ codes_out)
{
    __shared__ __align__(16) float sp[NCODE * ZC];  // [pair16][c16][lane2]
    __shared__ float sn[NCODE];
    __shared__ int   sh[NCODE];
    int tid = threadIdx.x;

    for (int i = tid; i < NCODE * ZC; i += blockDim.x) {
        int lane = i & 1;
        int c    = (i >> 1) & 15;
        int pr   = i >> 5;
        int e    = 2*pr + lane;
        float v = __ldg(&emb_in[e * ZC + c]);
        if (e == 0) v = 0.f;
        if (e == 1) v = 6.f;
        sp[i] = v;
    }
    if (tid < NCODE) sh[tid] = 0;
    __syncthreads();
    if (tid < NCODE) {
        int pr = tid >> 1, lane = tid & 1;
        float s = 0.f;
        for (int c = 0; c < ZC; c++) { float v = sp[pr*32 + c*2 + lane]; s += v * v; }
        sn[tid] = s;
    }
    __syncthreads();
    const u64* spp = (const u64*)sp;   // [pair16][c16]

    int p = blockIdx.x * blockDim.x + tid;   // 0..65535
    int b = p >> 12;
    int s = p & 4095;
    const float* zb = z + (long long)(b * ZC) * 4096 + s;

    float f[ZC];
    u64 f2[ZC];
    float fn = 0.f;
    #pragma unroll
    for (int c = 0; c < ZC; c++) {
        f[c] = zb[(long long)c * 4096];
        fn += f[c] * f[c];
        f2[c] = pack2(f[c], f[c]);
    }

    int best = 0; float bestd = INFINITY;
    #pragma unroll
    for (int pr = 0; pr < 16; pr++) {
        u64 dot2 = pack2(0.f, 0.f);
        #pragma unroll
        for (int c = 0; c < ZC; c++) fma2(dot2, f2[c], spp[pr*16 + c]);
        float dlo, dhi;
        unpack2(dot2, dlo, dhi);
        float d0 = fn - 2.f * dlo + sn[2*pr];
        float d1 = fn - 2.f * dhi + sn[2*pr + 1];
        if (d0 < bestd) { bestd = d0; best = 2*pr; }
        if (d1 < bestd) { bestd = d1; best = 2*pr + 1; }
    }

    codes_out[p] = (float)best;
    float* qb = quant + (long long)(b * ZC) * 4096 + s;
    int bpr = best >> 1, bln = best & 1;
    float diff2 = 0.f;
    #pragma unroll
    for (int c = 0; c < ZC; c++) {
        float e = sp[bpr*32 + c*2 + bln];
        qb[(long long)c * 4096] = e;
        float dvv = e - f[c];
        diff2 += dvv * dvv;
    }

    atomicAdd(&sh[best], 1);
    #pragma unroll
    for (int o = 16; o > 0; o >>= 1) diff2 += __shfl_down_sync(0xffffffff, diff2, o);
    if ((tid & 31) == 0) atomicAdd(&g_sqsum, diff2);
    __syncthreads();
    if (tid < NCODE) atomicAdd(&g_hist[tid], sh[tid]);
}

// ========================= deconv1 (R13, + finalize fold) =============================
// q (16,16,4,32,32) -> d1 (16,8,8,64,64), k4 s2 p1, relu
// idx bits: wg(4) | b_lo(1) | ho(6) | dd(3) | b_hi(3). 131072 thr, 1024x128
__global__ __launch_bounds__(128) void deconv1_kernel(
    const float* __restrict__ in, const float* __restrict__ w,
    const float* __restrict__ bias, float* __restrict__ out,
    const float* __restrict__ cluster_size, float* __restrict__ final_out)
{
    if (blockIdx.x == 0 && threadIdx.x == 0) {
        float invN = 1.f / (float)NPOS;
        float ent = 0.f;
        int used = 0;
        for (int i = 0; i < NCODE; i++) {
            float p = (float)g_hist[i] * invN;
            ent += p * logf(p + 1e-10f);
            if (__ldg(&cluster_size[i]) > 1e-5f) used++;
        }
        final_out[OUT_ELEMS] = 0.25f * g_sqsum / (float)(NPOS * ZC);
        final_out[OUT_ELEMS + 1 + NPOS] = expf(-ent);
        final_out[OUT_ELEMS + 2 + NPOS] = (float)used / (float)NCODE;
    }

    __shared__ __align__(16) float sw[8192];   // [ci16][kd4][kh4][p4][kw4][lane2]
    __shared__ float sb[8];
    for (int i = threadIdx.x; i < 8192; i += blockDim.x) {
        int lane = i & 1, kw = (i >> 1) & 3, p = (i >> 3) & 3,
            kh = (i >> 5) & 3, kd = (i >> 7) & 3, ci = i >> 9;
        int co = 2*p + lane;
        sw[i] = w[(((ci*8+co)*4+kd)*4+kh)*4+kw];
    }
    if (threadIdx.x < 8) sb[threadIdx.x] = bias[threadIdx.x];
    __syncthreads();
    const u64* sw8 = (const u64*)sw;

    int idx = blockIdx.x * blockDim.x + threadIdx.x;
    int wg = idx & 15;           // w0 = 4*wg
    int bl = (idx >> 4) & 1;
    int ho = (idx >> 5) & 63;
    int dd = (idx >> 11) & 7;
    int b  = ((idx >> 14) << 1) | bl;

    int ida = (dd + 1) >> 1, kda = (dd + 1) & 1;
    int iha = (ho + 1) >> 1, kha = (ho + 1) & 1;

    u64 acc[4][4];
    #pragma unroll
    for (int p = 0; p < 4; p++) {
        u64 bv = pack2(sb[2*p], sb[2*p+1]);
        #pragma unroll
        for (int j = 0; j < 4; j++) acc[p][j] = bv;
    }

    #pragma unroll
    for (int dt = 0; dt < 2; dt++) {
        int id = ida - dt, kd = kda + 2*dt;
        bool vd = (unsigned)id < 4u;
        int idc = vd ? id : 0;
        #pragma unroll
        for (int ht = 0; ht < 2; ht++) {
            int ih = iha - ht, kh = kha + 2*ht;
            bool vh = (unsigned)ih < 32u;
            bool v = vd && vh;
            int ihc = vh ? ih : 0;
            #pragma unroll
            for (int ci = 0; ci < 16; ci++) {
                const float* row = in + (long long)((b*16+ci)*4+idc)*1024 + ihc*32 + 2*wg;
                float2 V = *(const float2*)row;
                if (!v) { V.x = 0.f; V.y = 0.f; }
                float lv = __shfl_up_sync(0xffffffffu, V.y, 1, 16);
                float rv = __shfl_down_sync(0xffffffffu, V.x, 1, 16);
                if (wg == 0)  lv = 0.f;
                if (wg == 15) rv = 0.f;
                u64 s[4];
                s[0]=pack2(lv,lv); s[1]=pack2(V.x,V.x); s[2]=pack2(V.y,V.y); s[3]=pack2(rv,rv);
                int base = (((ci*4+kd)*4+kh)*4)*4;
                #pragma unroll
                for (int p = 0; p < 4; p++) {
                    const ulonglong2* wp = (const ulonglong2*)(sw8 + base + p*4);
                    ulonglong2 A = wp[0], B = wp[1];
                    u64 wk0 = A.x, wk1 = A.y, wk2 = B.x, wk3 = B.y;
                    fma2(acc[p][0], s[1], wk1); fma2(acc[p][0], s[0], wk3);
                    fma2(acc[p][1], s[2], wk0); fma2(acc[p][1], s[1], wk2);
                    fma2(acc[p][2], s[2], wk1); fma2(acc[p][2], s[1], wk3);
                    fma2(acc[p][3], s[3], wk0); fma2(acc[p][3], s[2], wk2);
                }
            }
        }
    }
    #pragma unroll
    for (int p = 0; p < 4; p++) {
        float lo[4], hi[4];
        #pragma unroll
        for (int j = 0; j < 4; j++) unpack2(acc[p][j], lo[j], hi[j]);
        float4 r0, r1;
        r0.x = fmaxf(lo[0],0.f); r0.y = fmaxf(lo[1],0.f); r0.z = fmaxf(lo[2],0.f); r0.w = fmaxf(lo[3],0.f);
        r1.x = fmaxf(hi[0],0.f); r1.y = fmaxf(hi[1],0.f); r1.z = fmaxf(hi[2],0.f); r1.w = fmaxf(hi[3],0.f);
        *(float4*)&out[(long long)((b*8+2*p  )*8+dd)*4096 + ho*64 + 4*wg] = r0;
        *(float4*)&out[(long long)((b*8+2*p+1)*8+dd)*4096 + ho*64 + 4*wg] = r1;
    }
}

// ========================= deconv3 (R13) =============================
// d1 (16,8,8,64,64) -> d2 (16,4,16,128,128), k4 s2 p1, relu
// idx bits: wg(5) | ho(7) | dd(4) | b(4). 1048576 thr, 4096x256
__global__ __launch_bounds__(256) void deconv3_kernel(
    const float* __restrict__ in, const float* __restrict__ w,
    const float* __restrict__ bias, float* __restrict__ out)
{
    __shared__ __align__(16) float sw[2048];   // [ci8][kd4][kh4][p2][kw4][lane2]
    __shared__ float sb[4];
    for (int i = threadIdx.x; i < 2048; i += blockDim.x) {
        int lane = i & 1, kw = (i >> 1) & 3, p = (i >> 3) & 1,
            kh = (i >> 4) & 3, kd = (i >> 6) & 3, ci = i >> 8;
        int co = 2*p + lane;
        sw[i] = w[(((ci*4+co)*4+kd)*4+kh)*4+kw];
    }
    if (threadIdx.x < 4) sb[threadIdx.x] = bias[threadIdx.x];
    __syncthreads();
    const u64* sw8 = (const u64*)sw;

    int idx = blockIdx.x * blockDim.x + threadIdx.x;
    int wg = idx & 31;            // w0 = 4*wg, lane == wg
    int ho = (idx >> 5) & 127;
    int dd = (idx >> 12) & 15;
    int b  = idx >> 16;

    int ida = (dd + 1) >> 1, kda = (dd + 1) & 1;
    int iha = (ho + 1) >> 1, kha = (ho + 1) & 1;

    u64 acc[2][4];
    #pragma unroll
    for (int p = 0; p < 2; p++) {
        u64 bv = pack2(sb[2*p], sb[2*p+1]);
        #pragma unroll
        for (int j = 0; j < 4; j++) acc[p][j] = bv;
    }

    #pragma unroll
    for (int dt = 0; dt < 2; dt++) {
        int id = ida - dt, kd = kda + 2*dt;
        bool vd = (unsigned)id < 8u;
        int idc = vd ? id : 0;
        #pragma unroll
        for (int ht = 0; ht < 2; ht++) {
            int ih = iha - ht, kh = kha + 2*ht;
            bool vh = (unsigned)ih < 64u;
            bool v = vd && vh;
            int ihc = vh ? ih : 0;
            #pragma unroll
            for (int ci = 0; ci < 8; ci++) {
                const float* row = in + (long long)((b*8+ci)*8+idc)*4096 + ihc*64 + 2*wg;
                float2 V = *(const float2*)row;
                if (!v) { V.x = 0.f; V.y = 0.f; }
                float lv = __shfl_up_sync(0xffffffffu, V.y, 1);
                float rv = __shfl_down_sync(0xffffffffu, V.x, 1);
                if (wg == 0)  lv = 0.f;
                if (wg == 31) rv = 0.f;
                u64 s[4];
                s[0]=pack2(lv,lv); s[1]=pack2(V.x,V.x); s[2]=pack2(V.y,V.y); s[3]=pack2(rv,rv);
                int base = (((ci*4+kd)*4+kh)*2)*4;
                #pragma unroll
                for (int p = 0; p < 2; p++) {
                    const ulonglong2* wp = (const ulonglong2*)(sw8 + base + p*4);
                    ulonglong2 A = wp[0], B = wp[1];
                    u64 wk0 = A.x, wk1 = A.y, wk2 = B.x, wk3 = B.y;
                    fma2(acc[p][0], s[1], wk1); fma2(acc[p][0], s[0], wk3);
                    fma2(acc[p][1], s[2], wk0); fma2(acc[p][1], s[1], wk2);
                    fma2(acc[p][2], s[2], wk1); fma2(acc[p][2], s[1], wk3);
                    fma2(acc[p][3], s[3], wk0); fma2(acc[p][3], s[2], wk2);
                }
            }
        }
    }
    #pragma unroll
    for (int p = 0; p < 2; p++) {
        float lo[4], hi[4];
        #pragma unroll
        for (int j = 0; j < 4; j++) unpack2(acc[p][j], lo[j], hi[j]);
        float4 r0, r1;
        r0.x = fmaxf(lo[0],0.f); r0.y = fmaxf(lo[1],0.f); r0.z = fmaxf(lo[2],0.f); r0.w = fmaxf(lo[3],0.f);
        r1.x = fmaxf(hi[0],0.f); r1.y = fmaxf(hi[1],0.f); r1.z = fmaxf(hi[2],0.f); r1.w = fmaxf(hi[3],0.f);
        *(float4*)&out[(long long)((b*4+2*p  )*16+dd)*16384 + ho*128 + 4*wg] = r0;
        *(float4*)&out[(long long)((b*4+2*p+1)*16+dd)*16384 + ho*128 + 4*wg] = r1;
    }
}

// ========================= deconv4 (R13) =============================
// d2 (16,4,16,128,128) -> out (16,3,16,128,128), k3 s1 p1, linear
// idx bits: wg(5) | ho(7) | dd(4) | b(4). 1048576 thr, 4096x256
__global__ __launch_bounds__(256) void deconv4_kernel(
    const float* __restrict__ in, const float* __restrict__ w,
    const float* __restrict__ bias, float* __restrict__ out)
{
    __shared__ __align__(16) float sw[576];   // [ci4][kd3][kh3][p2][kw4pad][lane2]
    __shared__ float sb[4];
    for (int i = threadIdx.x; i < 576; i += blockDim.x) {
        int lane = i & 1, kw = (i >> 1) & 3, p = (i >> 3) & 1;
        int r = i >> 4;
        int kh = r % 3; r /= 3;
        int kd = r % 3;
        int ci = r / 3;
        int co = 2*p + lane;
        sw[i] = (kw < 3 && co < 3) ? w[(((ci*3+co)*3+kd)*3+kh)*3+kw] : 0.f;
    }
    if (threadIdx.x < 4) sb[threadIdx.x] = (threadIdx.x < 3) ? bias[threadIdx.x] : 0.f;
    __syncthreads();
    const u64* sw8 = (const u64*)sw;

    int idx = blockIdx.x * blockDim.x + threadIdx.x;
    int wg = idx & 31;           // w0 = 4*wg, lane == wg
    int ho = (idx >> 5) & 127;
    int dd = (idx >> 12) & 15;
    int b  = idx >> 16;

    u64 acc[2][4];
    #pragma unroll
    for (int p = 0; p < 2; p++) {
        u64 bv = pack2(sb[2*p], sb[2*p+1]);
        #pragma unroll
        for (int j = 0; j < 4; j++) acc[p][j] = bv;
    }

    #pragma unroll
    for (int ci = 0; ci < 4; ci++) {
        const float* inc = in + (long long)((b*4+ci)*16) * 16384;
        #pragma unroll
        for (int kd = 0; kd < 3; kd++) {
            int id = dd + 1 - kd;
            bool vd = (unsigned)id < 16u;
            const float* incd = inc + (vd ? id : 0) * 16384;
            #pragma unroll
            for (int kh = 0; kh < 3; kh++) {
                int ih = ho + 1 - kh;
                bool vh = (unsigned)ih < 128u;
                bool v = vd && vh;
                const float* row = incd + (vh ? ih : 0)*128 + 4*wg;
                float4 A = *(const float4*)row;
                if (!v) { A.x=0.f;A.y=0.f;A.z=0.f;A.w=0.f; }
                float lv = __shfl_up_sync(0xffffffffu, A.w, 1);
                float rv = __shfl_down_sync(0xffffffffu, A.x, 1);
                if (wg == 0)  lv = 0.f;
                if (wg == 31) rv = 0.f;
                u64 s[6];
                s[0]=pack2(lv,lv); s[1]=pack2(A.x,A.x); s[2]=pack2(A.y,A.y);
                s[3]=pack2(A.z,A.z); s[4]=pack2(A.w,A.w); s[5]=pack2(rv,rv);
                int base = (((ci*3+kd)*3+kh)*2)*4;
                #pragma unroll
                for (int p = 0; p < 2; p++) {
                    const ulonglong2* wp = (const ulonglong2*)(sw8 + base + p*4);
                    ulonglong2 WA = wp[0];
                    u64 wk0 = WA.x, wk1 = WA.y, wk2 = sw8[base + p*4 + 2];
                    #pragma unroll
                    for (int j = 0; j < 4; j++) {
                        fma2(acc[p][j], s[j+2], wk0);
                        fma2(acc[p][j], s[j+1], wk1);
                        fma2(acc[p][j], s[j],   wk2);
                    }
                }
            }
        }
    }
    float lo0[4], hi0[4], lo1[4], hi1[4];
    #pragma unroll
    for (int j = 0; j < 4; j++) { unpack2(acc[0][j], lo0[j], hi0[j]); unpack2(acc[1][j], lo1[j], hi1[j]); }
    *(float4*)&out[(long long)((b*3+0)*16+dd)*16384 + ho*128 + 4*wg] = make_float4(lo0[0],lo0[1],lo0[2],lo0[3]);
    *(float4*)&out[(long long)((b*3+1)*16+dd)*16384 + ho*128 + 4*wg] = make_float4(hi0[0],hi0[1],hi0[2],hi0[3]);
    *(float4*)&out[(long long)((b*3+2)*16+dd)*16384 + ho*128 + 4*wg] = make_float4(lo1[0],lo1[1],lo1[2],lo1[3]);
}

// ---------------------------------------------------------------------------
extern "C" void kernel_launch(void* const* d_in, const int* in_sizes, int n_in,
                              void* d_out, int out_size)
{
    const float* x       = (const float*)d_in[0];
    const float* enc_w1  = (const float*)d_in[2];
    const float* enc_b1  = (const float*)d_in[3];
    const float* enc_w2  = (const float*)d_in[4];
    const float* enc_b2  = (const float*)d_in[5];
    const float* enc_w4  = (const float*)d_in[6];
    const float* enc_b4  = (const float*)d_in[7];
    const float* dec_w1  = (const float*)d_in[8];
    const float* dec_b1  = (const float*)d_in[9];
    const float* dec_w3  = (const float*)d_in[10];
    const float* dec_b3  = (const float*)d_in[11];
    const float* dec_w4  = (const float*)d_in[12];
    const float* dec_b4  = (const float*)d_in[13];
    const float* emb     = (const float*)d_in[14];
    const float* clsz    = (const float*)d_in[15];
    float* out = (float*)d_out;

    float *h1, *h2, *z, *q, *d1, *d2;
    cudaGetSymbolAddress((void**)&h1, g_h1);
    cudaGetSymbolAddress((void**)&h2, g_h2);
    cudaGetSymbolAddress((void**)&z,  g_z);
    cudaGetSymbolAddress((void**)&q,  g_q);
    cudaGetSymbolAddress((void**)&d1, g_d1);
    cudaGetSymbolAddress((void**)&d2, g_d2);

    conv1_kernel<<<1024, 128>>>(x, enc_w1, enc_b1, h1);
    conv2_kernel<<<1024, 128>>>(h1, enc_w2, enc_b2, h2);
    conv3_kernel<<<1024, 128>>>(h2, enc_w4, enc_b4, z);

    vq_kernel<<<512, 128>>>(z, emb, q, out + OUT_ELEMS + 1);

    deconv1_kernel<<<1024, 128>>>(q, dec_w1, dec_b1, d1, clsz, out);
    deconv3_kernel<<<4096, 256>>>(d1, dec_w3, dec_b3, d2);
    deconv4_kernel<<<4096, 256>>>(d2, dec_w4, dec_b4, out);
}

// round 17
// speedup vs baseline: 1.0365x; 1.0033x over previous
#include <cuda_runtime.h>
#include <math.h>

// ---------------------------------------------------------------------------
//  x:      (16, 3, 16, 128, 128)
//  h1:     (16, 4,  8,  64,  64)   conv k4 s2 p1 + relu
//  h2:     (16, 8,  4,  32,  32)   conv k4 s2 p1 + relu
//  z:      (16,16,  4,  32,  32)   conv k3 s1 p1 + clip[0,6]
//  codes:  (65536,) int            VQ argmin; quant NEVER materialized
//  d1:     (16, 8,  8,  64,  64)   deconv k4 s2 p1 + relu (gathers emb via codes)
//  d2:     (16, 4, 16, 128, 128)   deconv k4 s2 p1 + relu
//  out:    (16, 3, 16, 128, 128)   deconv k3 s1 p1
// ---------------------------------------------------------------------------

#define OUT_ELEMS (16*3*16*128*128)
#define NPOS      (16*4*32*32)
#define ZC        16
#define NCODE     32

typedef unsigned long long u64;

__device__ __forceinline__ u64 pack2(float lo, float hi) {
    u64 r; asm("mov.b64 %0, {%1,%2};" : "=l"(r) : "f"(lo), "f"(hi)); return r;
}
__device__ __forceinline__ void unpack2(u64 v, float& lo, float& hi) {
    asm("mov.b64 {%0,%1}, %2;" : "=f"(lo), "=f"(hi) : "l"(v));
}
__device__ __forceinline__ void fma2(u64& d, u64 a, u64 b) {
    asm("fma.rn.f32x2 %0, %1, %2, %0;" : "+l"(d) : "l"(a), "l"(b));
}

__device__ float g_h1[16*4*8*64*64];
__device__ float g_h2[16*8*4*32*32];
__device__ float g_z [16*16*4*32*32];
__device__ int   g_codes[NPOS];
__device__ float g_d1[16*8*8*64*64];
__device__ float g_d2[16*4*16*128*128];
__device__ float g_sqsum;
__device__ int   g_hist[NCODE];

// ========================= conv1 (R13) =============================
// x (16,3,16,128,128) -> h1 (16,4,8,64,64), k4 s2 p1, relu
// idx bits: wg(4) | b_lo(1) | h(6) | d(3) | b_hi(3). 131072 thr, 1024x128
__global__ __launch_bounds__(128) void conv1_kernel(
    const float* __restrict__ x, const float* __restrict__ w,
    const float* __restrict__ bias, float* __restrict__ out)
{
    if (blockIdx.x == 0) {
        if (threadIdx.x == 0) g_sqsum = 0.f;
        if (threadIdx.x < NCODE) g_hist[threadIdx.x] = 0;
    }

    __shared__ __align__(16) float sw[768];   // [ci3][kd4][kh4][p2][kw4][lane2]
    __shared__ float sb[4];
    for (int i = threadIdx.x; i < 768; i += blockDim.x) {
        int lane = i & 1, kw = (i >> 1) & 3, p = (i >> 3) & 1,
            kh = (i >> 4) & 3, kd = (i >> 6) & 3, ci = i >> 8;
        int co = 2*p + lane;
        sw[i] = w[(((co*3+ci)*4+kd)*4+kh)*4+kw];
    }
    if (threadIdx.x < 4) sb[threadIdx.x] = bias[threadIdx.x];
    __syncthreads();
    const u64* sw8 = (const u64*)sw;

    int idx = blockIdx.x * blockDim.x + threadIdx.x;
    int wg = idx & 15;
    int bl = (idx >> 4) & 1;
    int h  = (idx >> 5) & 63;
    int d  = (idx >> 11) & 7;
    int b  = ((idx >> 14) << 1) | bl;

    u64 acc[2][4];
    #pragma unroll
    for (int p = 0; p < 2; p++) {
        u64 bv = pack2(sb[2*p], sb[2*p+1]);
        #pragma unroll
        for (int j = 0; j < 4; j++) acc[p][j] = bv;
    }

    for (int ci = 0; ci < 3; ci++) {
        const float* inc = x + (long long)(b*3+ci) * 16 * 16384;
        #pragma unroll
        for (int kd = 0; kd < 4; kd++) {
            int id = 2*d - 1 + kd;
            bool vd = (unsigned)id < 16u;
            const float* incd = inc + (vd ? id : 0) * 16384;
            #pragma unroll
            for (int kh = 0; kh < 4; kh++) {
                int ih = 2*h - 1 + kh;
                bool vh = (unsigned)ih < 128u;
                bool v = vd && vh;
                const float* row = incd + (vh ? ih : 0)*128 + 8*wg;
                float4 A = *(const float4*)row;
                float4 B = *(const float4*)(row + 4);
                if (!v) { A.x=0.f;A.y=0.f;A.z=0.f;A.w=0.f; B=A; }
                float lv = __shfl_up_sync(0xffffffffu, B.w, 1, 16);
                float rv = __shfl_down_sync(0xffffffffu, A.x, 1, 16);
                if (wg == 0)  lv = 0.f;
                if (wg == 15) rv = 0.f;
                u64 s[10];
                s[0]=pack2(lv,lv);  s[1]=pack2(A.x,A.x); s[2]=pack2(A.y,A.y);
                s[3]=pack2(A.z,A.z); s[4]=pack2(A.w,A.w); s[5]=pack2(B.x,B.x);
                s[6]=pack2(B.y,B.y); s[7]=pack2(B.z,B.z); s[8]=pack2(B.w,B.w);
                s[9]=pack2(rv,rv);
                int base = (((ci*4+kd)*4+kh)*2)*4;
                #pragma unroll
                for (int p = 0; p < 2; p++) {
                    const ulonglong2* wp = (const ulonglong2*)(sw8 + base + p*4);
                    ulonglong2 WA = wp[0], WB = wp[1];
                    u64 wk[4] = {WA.x, WA.y, WB.x, WB.y};
                    #pragma unroll
                    for (int kw = 0; kw < 4; kw++)
                        #pragma unroll
                        for (int j = 0; j < 4; j++)
                            fma2(acc[p][j], s[2*j+kw], wk[kw]);
                }
            }
        }
    }
    #pragma unroll
    for (int p = 0; p < 2; p++) {
        float lo[4], hi[4];
        #pragma unroll
        for (int j = 0; j < 4; j++) unpack2(acc[p][j], lo[j], hi[j]);
        float4 r0, r1;
        r0.x = fmaxf(lo[0],0.f); r0.y = fmaxf(lo[1],0.f); r0.z = fmaxf(lo[2],0.f); r0.w = fmaxf(lo[3],0.f);
        r1.x = fmaxf(hi[0],0.f); r1.y = fmaxf(hi[1],0.f); r1.z = fmaxf(hi[2],0.f); r1.w = fmaxf(hi[3],0.f);
        *(float4*)&out[(long long)((b*4+2*p  )*8+d)*4096 + h*64 + 4*wg] = r0;
        *(float4*)&out[(long long)((b*4+2*p+1)*8+d)*4096 + h*64 + 4*wg] = r1;
    }
}

// ========================= conv2 (R13) =============================
// h1 (16,4,8,64,64) -> h2 (16,8,4,32,32), k4 s2 p1, relu
// idx bits: wg(4) | q(2) | h(5) | d(2) | b(4). 131072 thr, 1024x128
__global__ __launch_bounds__(128) void conv2_kernel(
    const float* __restrict__ in, const float* __restrict__ w,
    const float* __restrict__ bias, float* __restrict__ out)
{
    __shared__ __align__(16) float sw[2048];   // [ci4][kd4][kh4][q4][kw4][lane2]
    __shared__ float sb[8];
    for (int i = threadIdx.x; i < 2048; i += blockDim.x) {
        int lane = i & 1, kw = (i >> 1) & 3, q = (i >> 3) & 3,
            kh = (i >> 5) & 3, kd = (i >> 7) & 3, ci = i >> 9;
        int co = 2*q + lane;
        sw[i] = w[(((co*4+ci)*4+kd)*4+kh)*4+kw];
    }
    if (threadIdx.x < 8) sb[threadIdx.x] = bias[threadIdx.x];
    __syncthreads();
    const u64* sw8 = (const u64*)sw;

    int idx = blockIdx.x * blockDim.x + threadIdx.x;
    int wg = idx & 15;           // wo0 = 2*wg
    int q  = (idx >> 4) & 3;     // co pair
    int h  = (idx >> 6) & 31;
    int d  = (idx >> 11) & 3;
    int b  = idx >> 13;

    u64 acc[2];
    {
        u64 bv = pack2(sb[2*q], sb[2*q+1]);
        acc[0] = bv; acc[1] = bv;
    }

    #pragma unroll
    for (int ci = 0; ci < 4; ci++) {
        const float* inc = in + (long long)((b*4+ci)*8) * 4096;
        #pragma unroll
        for (int kd = 0; kd < 4; kd++) {
            int id = 2*d - 1 + kd;
            bool vd = (unsigned)id < 8u;
            const float* incd = inc + (vd ? id : 0) * 4096;
            #pragma unroll
            for (int kh = 0; kh < 4; kh++) {
                int ih = 2*h - 1 + kh;
                bool vh = (unsigned)ih < 64u;
                bool v = vd && vh;
                const float* row = incd + (vh ? ih : 0)*64 + 4*wg;
                float4 A = *(const float4*)row;
                if (!v) { A.x=0.f;A.y=0.f;A.z=0.f;A.w=0.f; }
                float lv = __shfl_up_sync(0xffffffffu, A.w, 1, 16);
                float rv = __shfl_down_sync(0xffffffffu, A.x, 1, 16);
                if (wg == 0)  lv = 0.f;
                if (wg == 15) rv = 0.f;
                u64 s[6];
                s[0]=pack2(lv,lv); s[1]=pack2(A.x,A.x); s[2]=pack2(A.y,A.y);
                s[3]=pack2(A.z,A.z); s[4]=pack2(A.w,A.w); s[5]=pack2(rv,rv);
                int base = (((ci*4+kd)*4+kh)*4+q)*4;
                const ulonglong2* wp = (const ulonglong2*)(sw8 + base);
                ulonglong2 WA = wp[0], WB = wp[1];
                u64 wk[4] = {WA.x, WA.y, WB.x, WB.y};
                #pragma unroll
                for (int kw = 0; kw < 4; kw++) {
                    fma2(acc[0], s[kw],   wk[kw]);
                    fma2(acc[1], s[2+kw], wk[kw]);
                }
            }
        }
    }
    float a0,b0,a1,b1;
    unpack2(acc[0], a0, b0);
    unpack2(acc[1], a1, b1);
    int co = 2*q;
    float2 r0, r1;
    r0.x = fmaxf(a0,0.f); r0.y = fmaxf(a1,0.f);
    r1.x = fmaxf(b0,0.f); r1.y = fmaxf(b1,0.f);
    *(float2*)&out[(long long)((b*8+co  )*4+d)*1024 + h*32 + 2*wg] = r0;
    *(float2*)&out[(long long)((b*8+co+1)*4+d)*1024 + h*32 + 2*wg] = r1;
}

// ========================= conv3 (R13) =============================
// h2 (16,8,4,32,32) -> z (16,16,4,32,32), k3 s1 p1, clip[0,6]
// idx bits: wg(3) | q(3) | h(5) | d(2) | b(4). 131072 thr, 1024x128
__global__ __launch_bounds__(128) void conv3_kernel(
    const float* __restrict__ in, const float* __restrict__ w,
    const float* __restrict__ bias, float* __restrict__ out)
{
    __shared__ __align__(16) float sw[3456];   // [ci8][kd3][kh3][q8][kw3][lane2]
    __shared__ float sb[16];
    for (int i = threadIdx.x; i < 3456; i += blockDim.x) {
        int lane = i & 1;
        int r = i >> 1;
        int kw = r % 3; r /= 3;
        int q = r & 7; r >>= 3;
        int kh = r % 3; r /= 3;
        int kd = r % 3;
        int ci = r / 3;
        int co = 2*q + lane;
        sw[i] = w[(((co*8+ci)*3+kd)*3+kh)*3+kw];
    }
    if (threadIdx.x < 16) sb[threadIdx.x] = bias[threadIdx.x];
    __syncthreads();
    const u64* sw8 = (const u64*)sw;

    int idx = blockIdx.x * blockDim.x + threadIdx.x;
    int wg = idx & 7;            // wo0 = 4*wg
    int q  = (idx >> 3) & 7;     // co pair
    int h  = (idx >> 6) & 31;
    int d  = (idx >> 11) & 3;
    int b  = idx >> 13;

    u64 acc[4];
    {
        u64 bv = pack2(sb[2*q], sb[2*q+1]);
        #pragma unroll
        for (int j = 0; j < 4; j++) acc[j] = bv;
    }

    #pragma unroll
    for (int ci = 0; ci < 8; ci++) {
        const float* inc = in + (long long)((b*8+ci)*4) * 1024;
        #pragma unroll
        for (int kd = 0; kd < 3; kd++) {
            int id = d - 1 + kd;
            bool vd = (unsigned)id < 4u;
            const float* incd = inc + (vd ? id : 0) * 1024;
            #pragma unroll
            for (int kh = 0; kh < 3; kh++) {
                int ih = h - 1 + kh;
                bool vh = (unsigned)ih < 32u;
                bool v = vd && vh;
                const float* row = incd + (vh ? ih : 0)*32 + 4*wg;
                float4 A = *(const float4*)row;
                if (!v) { A.x=0.f;A.y=0.f;A.z=0.f;A.w=0.f; }
                float lv = __shfl_up_sync(0xffffffffu, A.w, 1, 8);
                float rv = __shfl_down_sync(0xffffffffu, A.x, 1, 8);
                if (wg == 0) lv = 0.f;
                if (wg == 7) rv = 0.f;
                u64 s[6];
                s[0]=pack2(lv,lv); s[1]=pack2(A.x,A.x); s[2]=pack2(A.y,A.y);
                s[3]=pack2(A.z,A.z); s[4]=pack2(A.w,A.w); s[5]=pack2(rv,rv);
                int base = ((((ci*3+kd)*3+kh)*8+q))*3;
                u64 wk0 = sw8[base], wk1 = sw8[base + 1], wk2 = sw8[base + 2];
                #pragma unroll
                for (int j = 0; j < 4; j++) {
                    fma2(acc[j], s[j],   wk0);
                    fma2(acc[j], s[j+1], wk1);
                    fma2(acc[j], s[j+2], wk2);
                }
            }
        }
    }
    float lo[4], hi[4];
    #pragma unroll
    for (int j = 0; j < 4; j++) unpack2(acc[j], lo[j], hi[j]);
    float4 r0, r1;
    r0.x = fminf(fmaxf(lo[0],0.f),6.f); r0.y = fminf(fmaxf(lo[1],0.f),6.f);
    r0.z = fminf(fmaxf(lo[2],0.f),6.f); r0.w = fminf(fmaxf(lo[3],0.f),6.f);
    r1.x = fminf(fmaxf(hi[0],0.f),6.f); r1.y = fminf(fmaxf(hi[1],0.f),6.f);
    r1.z = fminf(fmaxf(hi[2],0.f),6.f); r1.w = fminf(fmaxf(hi[3],0.f),6.f);
    int co = 2*q;
    *(float4*)&out[(long long)((b*16+co  )*4+d)*1024 + h*32 + 4*wg] = r0;
    *(float4*)&out[(long long)((b*16+co+1)*4+d)*1024 + h*32 + 4*wg] = r1;
}

// ========================= VQ (R17: f32x2 pairs, no quant write) =============================
__global__ __launch_bounds__(128) void vq_kernel(
    const float* __restrict__ z, const float* __restrict__ emb_in,
    int* __restrict__ codes_int, float* __restrict__ codes_out)
{
    __shared__ __align__(16) float sp[NCODE * ZC];  // [pair16][c16][lane2]
    __shared__ float sn[NCODE];
    __shared__ int   sh[NCODE];
    int tid = threadIdx.x;

    for (int i = tid; i < NCODE * ZC; i += blockDim.x) {
        int lane = i & 1;
        int c    = (i >> 1) & 15;
        int pr   = i >> 5;
        int e    = 2*pr + lane;
        float v = __ldg(&emb_in[e * ZC + c]);
        if (e == 0) v = 0.f;
        if (e == 1) v = 6.f;
        sp[i] = v;
    }
    if (tid < NCODE) sh[tid] = 0;
    __syncthreads();
    if (tid < NCODE) {
        int pr = tid >> 1, lane = tid & 1;
        float s = 0.f;
        for (int c = 0; c < ZC; c++) { float v = sp[pr*32 + c*2 + lane]; s += v * v; }
        sn[tid] = s;
    }
    __syncthreads();
    const u64* spp = (const u64*)sp;   // [pair16][c16]

    int p = blockIdx.x * blockDim.x + tid;   // 0..65535
    int b = p >> 12;
    int s = p & 4095;
    const float* zb = z + (long long)(b * ZC) * 4096 + s;

    float f[ZC];
    u64 f2[ZC];
    float fn = 0.f;
    #pragma unroll
    for (int c = 0; c < ZC; c++) {
        f[c] = zb[(long long)c * 4096];
        fn += f[c] * f[c];
        f2[c] = pack2(f[c], f[c]);
    }

    int best = 0; float bestd = INFINITY;
    #pragma unroll
    for (int pr = 0; pr < 16; pr++) {
        u64 dot2 = pack2(0.f, 0.f);
        #pragma unroll
        for (int c = 0; c < ZC; c++) fma2(dot2, f2[c], spp[pr*16 + c]);
        float dlo, dhi;
        unpack2(dot2, dlo, dhi);
        float d0 = fn - 2.f * dlo + sn[2*pr];
        float d1 = fn - 2.f * dhi + sn[2*pr + 1];
        if (d0 < bestd) { bestd = d0; best = 2*pr; }
        if (d1 < bestd) { bestd = d1; best = 2*pr + 1; }
    }

    codes_out[p] = (float)best;
    codes_int[p] = best;
    int bpr = best >> 1, bln = best & 1;
    float diff2 = 0.f;
    #pragma unroll
    for (int c = 0; c < ZC; c++) {
        float e = sp[bpr*32 + c*2 + bln];
        float dvv = e - f[c];
        diff2 += dvv * dvv;
    }

    atomicAdd(&sh[best], 1);
    #pragma unroll
    for (int o = 16; o > 0; o >>= 1) diff2 += __shfl_down_sync(0xffffffff, diff2, o);
    if ((tid & 31) == 0) atomicAdd(&g_sqsum, diff2);
    __syncthreads();
    if (tid < NCODE) atomicAdd(&g_hist[tid], sh[tid]);
}

// ========================= deconv1 (R17: code-gather, + finalize fold) =============================
// codes (65536) -> d1 (16,8,8,64,64), k4 s2 p1, relu
// quant[ci][pos] == se[ci][codes[pos]]; code 0 row is all-zero, so invalid
// taps / halo use code 0. idx bits as R13. 131072 thr, 1024x128
__global__ __launch_bounds__(128) void deconv1_kernel(
    const int* __restrict__ codes, const float* __restrict__ emb_in,
    const float* __restrict__ w, const float* __restrict__ bias,
    float* __restrict__ out,
    const float* __restrict__ cluster_size, float* __restrict__ final_out)
{
    if (blockIdx.x == 0 && threadIdx.x == 0) {
        float invN = 1.f / (float)NPOS;
        float ent = 0.f;
        int used = 0;
        for (int i = 0; i < NCODE; i++) {
            float p = (float)g_hist[i] * invN;
            ent += p * logf(p + 1e-10f);
            if (__ldg(&cluster_size[i]) > 1e-5f) used++;
        }
        final_out[OUT_ELEMS] = 0.25f * g_sqsum / (float)(NPOS * ZC);
        final_out[OUT_ELEMS + 1 + NPOS] = expf(-ent);
        final_out[OUT_ELEMS + 2 + NPOS] = (float)used / (float)NCODE;
    }

    __shared__ __align__(16) float sw[8192];   // [ci16][kd4][kh4][p4][kw4][lane2]
    __shared__ float se[ZC * NCODE];           // [ci16][code32] — conflict-free gather
    __shared__ float sb[8];
    for (int i = threadIdx.x; i < 8192; i += blockDim.x) {
        int lane = i & 1, kw = (i >> 1) & 3, p = (i >> 3) & 3,
            kh = (i >> 5) & 3, kd = (i >> 7) & 3, ci = i >> 9;
        int co = 2*p + lane;
        sw[i] = w[(((ci*8+co)*4+kd)*4+kh)*4+kw];
    }
    for (int i = threadIdx.x; i < ZC * NCODE; i += blockDim.x) {
        int ci = i >> 5, e = i & 31;
        float v = __ldg(&emb_in[e * ZC + ci]);
        if (e == 0) v = 0.f;
        if (e == 1) v = 6.f;
        se[i] = v;
    }
    if (threadIdx.x < 8) sb[threadIdx.x] = bias[threadIdx.x];
    __syncthreads();
    const u64* sw8 = (const u64*)sw;

    int idx = blockIdx.x * blockDim.x + threadIdx.x;
    int wg = idx & 15;           // w0 = 4*wg, input iw0 = 2*wg
    int bl = (idx >> 4) & 1;
    int ho = (idx >> 5) & 63;
    int dd = (idx >> 11) & 7;
    int b  = ((idx >> 14) << 1) | bl;

    int ida = (dd + 1) >> 1, kda = (dd + 1) & 1;
    int iha = (ho + 1) >> 1, kha = (ho + 1) & 1;

    u64 acc[4][4];
    #pragma unroll
    for (int p = 0; p < 4; p++) {
        u64 bv = pack2(sb[2*p], sb[2*p+1]);
        #pragma unroll
        for (int j = 0; j < 4; j++) acc[p][j] = bv;
    }

    #pragma unroll
    for (int dt = 0; dt < 2; dt++) {
        int id = ida - dt, kd = kda + 2*dt;
        bool vd = (unsigned)id < 4u;
        int idc = vd ? id : 0;
        #pragma unroll
        for (int ht = 0; ht < 2; ht++) {
            int ih = iha - ht, kh = kha + 2*ht;
            bool vh = (unsigned)ih < 32u;
            bool v = vd && vh;
            int ihc = vh ? ih : 0;
            // one int2 of codes replaces 16 float2 LDGs
            const int* crow = codes + (b*4 + idc)*1024 + ihc*32 + 2*wg;
            int2 C = *(const int2*)crow;
            int lc = __shfl_up_sync(0xffffffffu, C.y, 1, 16);
            int rc = __shfl_down_sync(0xffffffffu, C.x, 1, 16);
            if (wg == 0)  lc = 0;
            if (wg == 15) rc = 0;
            if (!v) { C.x = 0; C.y = 0; lc = 0; rc = 0; }
            #pragma unroll
            for (int ci = 0; ci < 16; ci++) {
                const float* sec = se + ci*32;
                float v0 = sec[lc], v1 = sec[C.x], v2 = sec[C.y], v3 = sec[rc];
                u64 s[4];
                s[0]=pack2(v0,v0); s[1]=pack2(v1,v1); s[2]=pack2(v2,v2); s[3]=pack2(v3,v3);
                int base = (((ci*4+kd)*4+kh)*4)*4;
                #pragma unroll
                for (int p = 0; p < 4; p++) {
                    const ulonglong2* wp = (const ulonglong2*)(sw8 + base + p*4);
                    ulonglong2 A = wp[0], B = wp[1];
                    u64 wk0 = A.x, wk1 = A.y, wk2 = B.x, wk3 = B.y;
                    fma2(acc[p][0], s[1], wk1); fma2(acc[p][0], s[0], wk3);
                    fma2(acc[p][1], s[2], wk0); fma2(acc[p][1], s[1], wk2);
                    fma2(acc[p][2], s[2], wk1); fma2(acc[p][2], s[1], wk3);
                    fma2(acc[p][3], s[3], wk0); fma2(acc[p][3], s[2], wk2);
                }
            }
        }
    }
    #pragma unroll
    for (int p = 0; p < 4; p++) {
        float lo[4], hi[4];
        #pragma unroll
        for (int j = 0; j < 4; j++) unpack2(acc[p][j], lo[j], hi[j]);
        float4 r0, r1;
        r0.x = fmaxf(lo[0],0.f); r0.y = fmaxf(lo[1],0.f); r0.z = fmaxf(lo[2],0.f); r0.w = fmaxf(lo[3],0.f);
        r1.x = fmaxf(hi[0],0.f); r1.y = fmaxf(hi[1],0.f); r1.z = fmaxf(hi[2],0.f); r1.w = fmaxf(hi[3],0.f);
        *(float4*)&out[(long long)((b*8+2*p  )*8+dd)*4096 + ho*64 + 4*wg] = r0;
        *(float4*)&out[(long long)((b*8+2*p+1)*8+dd)*4096 + ho*64 + 4*wg] = r1;
    }
}

// ========================= deconv3 (R13) =============================
// d1 (16,8,8,64,64) -> d2 (16,4,16,128,128), k4 s2 p1, relu
// idx bits: wg(5) | ho(7) | dd(4) | b(4). 1048576 thr, 4096x256
__global__ __launch_bounds__(256) void deconv3_kernel(
    const float* __restrict__ in, const float* __restrict__ w,
    const float* __restrict__ bias, float* __restrict__ out)
{
    __shared__ __align__(16) float sw[2048];   // [ci8][kd4][kh4][p2][kw4][lane2]
    __shared__ float sb[4];
    for (int i = threadIdx.x; i < 2048; i += blockDim.x) {
        int lane = i & 1, kw = (i >> 1) & 3, p = (i >> 3) & 1,
            kh = (i >> 4) & 3, kd = (i >> 6) & 3, ci = i >> 8;
        int co = 2*p + lane;
        sw[i] = w[(((ci*4+co)*4+kd)*4+kh)*4+kw];
    }
    if (threadIdx.x < 4) sb[threadIdx.x] = bias[threadIdx.x];
    __syncthreads();
    const u64* sw8 = (const u64*)sw;

    int idx = blockIdx.x * blockDim.x + threadIdx.x;
    int wg = idx & 31;            // w0 = 4*wg, lane == wg
    int ho = (idx >> 5) & 127;
    int dd = (idx >> 12) & 15;
    int b  = idx >> 16;

    int ida = (dd + 1) >> 1, kda = (dd + 1) & 1;
    int iha = (ho + 1) >> 1, kha = (ho + 1) & 1;

    u64 acc[2][4];
    #pragma unroll
    for (int p = 0; p < 2; p++) {
        u64 bv = pack2(sb[2*p], sb[2*p+1]);
        #pragma unroll
        for (int j = 0; j < 4; j++) acc[p][j] = bv;
    }

    #pragma unroll
    for (int dt = 0; dt < 2; dt++) {
        int id = ida - dt, kd = kda + 2*dt;
        bool vd = (unsigned)id < 8u;
        int idc = vd ? id : 0;
        #pragma unroll
        for (int ht = 0; ht < 2; ht++) {
            int ih = iha - ht, kh = kha + 2*ht;
            bool vh = (unsigned)ih < 64u;
            bool v = vd && vh;
            int ihc = vh ? ih : 0;
            #pragma unroll
            for (int ci = 0; ci < 8; ci++) {
                const float* row = in + (long long)((b*8+ci)*8+idc)*4096 + ihc*64 + 2*wg;
                float2 V = *(const float2*)row;
                if (!v) { V.x = 0.f; V.y = 0.f; }
                float lv = __shfl_up_sync(0xffffffffu, V.y, 1);
                float rv = __shfl_down_sync(0xffffffffu, V.x, 1);
                if (wg == 0)  lv = 0.f;
                if (wg == 31) rv = 0.f;
                u64 s[4];
                s[0]=pack2(lv,lv); s[1]=pack2(V.x,V.x); s[2]=pack2(V.y,V.y); s[3]=pack2(rv,rv);
                int base = (((ci*4+kd)*4+kh)*2)*4;
                #pragma unroll
                for (int p = 0; p < 2; p++) {
                    const ulonglong2* wp = (const ulonglong2*)(sw8 + base + p*4);
                    ulonglong2 A = wp[0], B = wp[1];
                    u64 wk0 = A.x, wk1 = A.y, wk2 = B.x, wk3 = B.y;
                    fma2(acc[p][0], s[1], wk1); fma2(acc[p][0], s[0], wk3);
                    fma2(acc[p][1], s[2], wk0); fma2(acc[p][1], s[1], wk2);
                    fma2(acc[p][2], s[2], wk1); fma2(acc[p][2], s[1], wk3);
                    fma2(acc[p][3], s[3], wk0); fma2(acc[p][3], s[2], wk2);
                }
            }
        }
    }
    #pragma unroll
    for (int p = 0; p < 2; p++) {
        float lo[4], hi[4];
        #pragma unroll
        for (int j = 0; j < 4; j++) unpack2(acc[p][j], lo[j], hi[j]);
        float4 r0, r1;
        r0.x = fmaxf(lo[0],0.f); r0.y = fmaxf(lo[1],0.f); r0.z = fmaxf(lo[2],0.f); r0.w = fmaxf(lo[3],0.f);
        r1.x = fmaxf(hi[0],0.f); r1.y = fmaxf(hi[1],0.f); r1.z = fmaxf(hi[2],0.f); r1.w = fmaxf(hi[3],0.f);
        *(float4*)&out[(long long)((b*4+2*p  )*16+dd)*16384 + ho*128 + 4*wg] = r0;
        *(float4*)&out[(long long)((b*4+2*p+1)*16+dd)*16384 + ho*128 + 4*wg] = r1;
    }
}

// ========================= deconv4 (R13) =============================
// d2 (16,4,16,128,128) -> out (16,3,16,128,128), k3 s1 p1, linear
// idx bits: wg(5) | ho(7) | dd(4) | b(4). 1048576 thr, 4096x256
__global__ __launch_bounds__(256) void deconv4_kernel(
    const float* __restrict__ in, const float* __restrict__ w,
    const float* __restrict__ bias, float* __restrict__ out)
{
    __shared__ __align__(16) float sw[576];   // [ci4][kd3][kh3][p2][kw4pad][lane2]
    __shared__ float sb[4];
    for (int i = threadIdx.x; i < 576; i += blockDim.x) {
        int lane = i & 1, kw = (i >> 1) & 3, p = (i >> 3) & 1;
        int r = i >> 4;
        int kh = r % 3; r /= 3;
        int kd = r % 3;
        int ci = r / 3;
        int co = 2*p + lane;
        sw[i] = (kw < 3 && co < 3) ? w[(((ci*3+co)*3+kd)*3+kh)*3+kw] : 0.f;
    }
    if (threadIdx.x < 4) sb[threadIdx.x] = (threadIdx.x < 3) ? bias[threadIdx.x] : 0.f;
    __syncthreads();
    const u64* sw8 = (const u64*)sw;

    int idx = blockIdx.x * blockDim.x + threadIdx.x;
    int wg = idx & 31;           // w0 = 4*wg, lane == wg
    int ho = (idx >> 5) & 127;
    int dd = (idx >> 12) & 15;
    int b  = idx >> 16;

    u64 acc[2][4];
    #pragma unroll
    for (int p = 0; p < 2; p++) {
        u64 bv = pack2(sb[2*p], sb[2*p+1]);
        #pragma unroll
        for (int j = 0; j < 4; j++) acc[p][j] = bv;
    }

    #pragma unroll
    for (int ci = 0; ci < 4; ci++) {
        const float* inc = in + (long long)((b*4+ci)*16) * 16384;
        #pragma unroll
        for (int kd = 0; kd < 3; kd++) {
            int id = dd + 1 - kd;
            bool vd = (unsigned)id < 16u;
            const float* incd = inc + (vd ? id : 0) * 16384;
            #pragma unroll
            for (int kh = 0; kh < 3; kh++) {
                int ih = ho + 1 - kh;
                bool vh = (unsigned)ih < 128u;
                bool v = vd && vh;
                const float* row = incd + (vh ? ih : 0)*128 + 4*wg;
                float4 A = *(const float4*)row;
                if (!v) { A.x=0.f;A.y=0.f;A.z=0.f;A.w=0.f; }
                float lv = __shfl_up_sync(0xffffffffu, A.w, 1);
                float rv = __shfl_down_sync(0xffffffffu, A.x, 1);
                if (wg == 0)  lv = 0.f;
                if (wg == 31) rv = 0.f;
                u64 s[6];
                s[0]=pack2(lv,lv); s[1]=pack2(A.x,A.x); s[2]=pack2(A.y,A.y);
                s[3]=pack2(A.z,A.z); s[4]=pack2(A.w,A.w); s[5]=pack2(rv,rv);
                int base = (((ci*3+kd)*3+kh)*2)*4;
                #pragma unroll
                for (int p = 0; p < 2; p++) {
                    const ulonglong2* wp = (const ulonglong2*)(sw8 + base + p*4);
                    ulonglong2 WA = wp[0];
                    u64 wk0 = WA.x, wk1 = WA.y, wk2 = sw8[base + p*4 + 2];
                    #pragma unroll
                    for (int j = 0; j < 4; j++) {
                        fma2(acc[p][j], s[j+2], wk0);
                        fma2(acc[p][j], s[j+1], wk1);
                        fma2(acc[p][j], s[j],   wk2);
                    }
                }
            }
        }
    }
    float lo0[4], hi0[4], lo1[4], hi1[4];
    #pragma unroll
    for (int j = 0; j < 4; j++) { unpack2(acc[0][j], lo0[j], hi0[j]); unpack2(acc[1][j], lo1[j], hi1[j]); }
    *(float4*)&out[(long long)((b*3+0)*16+dd)*16384 + ho*128 + 4*wg] = make_float4(lo0[0],lo0[1],lo0[2],lo0[3]);
    *(float4*)&out[(long long)((b*3+1)*16+dd)*16384 + ho*128 + 4*wg] = make_float4(hi0[0],hi0[1],hi0[2],hi0[3]);
    *(float4*)&out[(long long)((b*3+2)*16+dd)*16384 + ho*128 + 4*wg] = make_float4(lo1[0],lo1[1],lo1[2],lo1[3]);
}

// ---------------------------------------------------------------------------
extern "C" void kernel_launch(void* const* d_in, const int* in_sizes, int n_in,
                              void* d_out, int out_size)
{
    const float* x       = (const float*)d_in[0];
    const float* enc_w1  = (const float*)d_in[2];
    const float* enc_b1  = (const float*)d_in[3];
    const float* enc_w2  = (const float*)d_in[4];
    const float* enc_b2  = (const float*)d_in[5];
    const float* enc_w4  = (const float*)d_in[6];
    const float* enc_b4  = (const float*)d_in[7];
    const float* dec_w1  = (const float*)d_in[8];
    const float* dec_b1  = (const float*)d_in[9];
    const float* dec_w3  = (const float*)d_in[10];
    const float* dec_b3  = (const float*)d_in[11];
    const float* dec_w4  = (const float*)d_in[12];
    const float* dec_b4  = (const float*)d_in[13];
    const float* emb     = (const float*)d_in[14];
    const float* clsz    = (const float*)d_in[15];
    float* out = (float*)d_out;

    float *h1, *h2, *z, *d1, *d2;
    int *codes;
    cudaGetSymbolAddress((void**)&h1, g_h1);
    cudaGetSymbolAddress((void**)&h2, g_h2);
    cudaGetSymbolAddress((void**)&z,  g_z);
    cudaGetSymbolAddress((void**)&codes, g_codes);
    cudaGetSymbolAddress((void**)&d1, g_d1);
    cudaGetSymbolAddress((void**)&d2, g_d2);

    conv1_kernel<<<1024, 128>>>(x, enc_w1, enc_b1, h1);
    conv2_kernel<<<1024, 128>>>(h1, enc_w2, enc_b2, h2);
    conv3_kernel<<<1024, 128>>>(h2, enc_w4, enc_b4, z);

    vq_kernel<<<512, 128>>>(z, emb, codes, out + OUT_ELEMS + 1);

    deconv1_kernel<<<1024, 128>>>(codes, emb, dec_w1, dec_b1, d1, clsz, out);
    deconv3_kernel<<<4096, 256>>>(d1, dec_w3, dec_b3, d2);
    deconv4_kernel<<<4096, 256>>>(d2, dec_w4, dec_b4, out);
}